// round 7
// baseline (speedup 1.0000x reference)
#include <cuda_runtime.h>
#include <cuda_bf16.h>
#include <math.h>

#define U_DIM 4096
#define T_DIM 200
#define K_DIM 64
#define Q_DIM 10000
#define H_DIM 128

// Scratch (device globals; no allocation in kernel_launch)
__device__ float2 d_tab[2 * Q_DIM];              // (mu, r) per (q, resp)
__device__ unsigned char d_kcq[Q_DIM];           // kc per question
__device__ float4 d_sc[T_DIM * U_DIM];           // (mu, r, ts, td) in (T,U) layout
__device__ float4 d_bc[T_DIM * U_DIM];           // (b, c, ts, td) in (T,U) layout
__device__ unsigned char d_kcsc[T_DIM * U_DIM];  // kc in (T,U) layout

__device__ __forceinline__ float gelu_exact(float x) {
    return 0.5f * x * (1.0f + erff(x * 0.70710678118654752440f));
}

// ---------------------------------------------------------------------------
// Kernel A: per-(q,resp) MLP table + kc_of_q.
// One warp per 4 tasks (2 questions x resp {0,1}). Lane owns hidden units
// 4*lane..4*lane+3 (float4 weight loads); layer-2 h broadcast via shfl.
// kmap arrives as int32-upconverted bool: test != 0.
// ---------------------------------------------------------------------------
__global__ void __launch_bounds__(256) mlp_table_kernel(
    const float* __restrict__ dmu, const float* __restrict__ smu,
    const int* __restrict__ kmap,
    const float* __restrict__ W1, const float* __restrict__ b1,
    const float* __restrict__ W2, const float* __restrict__ b2,
    const float* __restrict__ W3, const float* __restrict__ b3)
{
    for (int q = blockIdx.x * blockDim.x + threadIdx.x; q < Q_DIM;
         q += gridDim.x * blockDim.x) {
        int kc = 0;
        #pragma unroll 8
        for (int k = K_DIM - 1; k >= 0; k--) {
            if (kmap[q * K_DIM + k] != 0) kc = k;
        }
        d_kcq[q] = (unsigned char)kc;
    }

    const int lane = threadIdx.x & 31;
    const int gw = (blockIdx.x * blockDim.x + threadIdx.x) >> 5;
    if (gw >= Q_DIM / 2) return;
    const int q0 = gw * 2;

    const float x0a = dmu[q0],     x1a = smu[q0];
    const float x0b = dmu[q0 + 1], x1b = smu[q0 + 1];

    // ---- layer 1 ----
    const float4 w10 = *(const float4*)(W1 + 0 * H_DIM + 4 * lane);
    const float4 w11 = *(const float4*)(W1 + 1 * H_DIM + 4 * lane);
    const float4 w12 = *(const float4*)(W1 + 2 * H_DIM + 4 * lane);
    const float4 b1v = *(const float4*)(b1 + 4 * lane);
    float r0[4] = {w10.x, w10.y, w10.z, w10.w};
    float r1[4] = {w11.x, w11.y, w11.z, w11.w};
    float r2[4] = {w12.x, w12.y, w12.z, w12.w};
    float bb[4] = {b1v.x, b1v.y, b1v.z, b1v.w};

    float h[4][4];
    #pragma unroll
    for (int e = 0; e < 4; e++) {
        float ba  = fmaf(x0a, r0[e], fmaf(x1a, r1[e], bb[e]));
        float bbq = fmaf(x0b, r0[e], fmaf(x1b, r1[e], bb[e]));
        h[0][e] = gelu_exact(ba);
        h[1][e] = gelu_exact(ba + r2[e]);
        h[2][e] = gelu_exact(bbq);
        h[3][e] = gelu_exact(bbq + r2[e]);
    }

    // ---- layer 2: 128x128 dense ----
    const float4 b2v = *(const float4*)(b2 + 4 * lane);
    float acc[4][4];
    #pragma unroll
    for (int t = 0; t < 4; t++) {
        acc[t][0] = b2v.x; acc[t][1] = b2v.y;
        acc[t][2] = b2v.z; acc[t][3] = b2v.w;
    }
    #pragma unroll 4
    for (int base = 0; base < 32; base++) {
        float4 w2r[4];
        #pragma unroll
        for (int ii = 0; ii < 4; ii++)
            w2r[ii] = *(const float4*)(W2 + (base * 4 + ii) * H_DIM + 4 * lane);
        #pragma unroll
        for (int t = 0; t < 4; t++) {
            #pragma unroll
            for (int ii = 0; ii < 4; ii++) {
                float hv = __shfl_sync(0xFFFFFFFFu, h[t][ii], base);
                acc[t][0] = fmaf(hv, w2r[ii].x, acc[t][0]);
                acc[t][1] = fmaf(hv, w2r[ii].y, acc[t][1]);
                acc[t][2] = fmaf(hv, w2r[ii].z, acc[t][2]);
                acc[t][3] = fmaf(hv, w2r[ii].w, acc[t][3]);
            }
        }
    }
    float h2[4][4];
    #pragma unroll
    for (int t = 0; t < 4; t++)
        #pragma unroll
        for (int e = 0; e < 4; e++)
            h2[t][e] = gelu_exact(acc[t][e]);

    // ---- layer 3: 128 -> 2 ----
    const float4 w3a = *(const float4*)(W3 + 8 * lane);
    const float4 w3b = *(const float4*)(W3 + 8 * lane + 4);
    const float b30 = b3[0], b31 = b3[1];

    float o0[4], o1[4];
    #pragma unroll
    for (int t = 0; t < 4; t++) {
        o0[t] = fmaf(h2[t][0], w3a.x, fmaf(h2[t][1], w3a.z,
                fmaf(h2[t][2], w3b.x, h2[t][3] * w3b.z)));
        o1[t] = fmaf(h2[t][0], w3a.y, fmaf(h2[t][1], w3a.w,
                fmaf(h2[t][2], w3b.y, h2[t][3] * w3b.w)));
    }
    #pragma unroll
    for (int off = 16; off; off >>= 1) {
        #pragma unroll
        for (int t = 0; t < 4; t++) {
            o0[t] += __shfl_xor_sync(0xFFFFFFFFu, o0[t], off);
            o1[t] += __shfl_xor_sync(0xFFFFFFFFu, o1[t], off);
        }
    }
    if (lane == 0) {
        #pragma unroll
        for (int t = 0; t < 4; t++) {
            float mu = gelu_exact(o0[t] + b30);
            float lv = gelu_exact(o1[t] + b31);
            float s = fmaxf(expf(0.5f * lv), 1e-8f);
            float inv = 1.0f / s;
            d_tab[4 * gw + t] = make_float2(mu, inv * inv);
        }
    }
}

// ---------------------------------------------------------------------------
// Kernel B: tiled transpose gather. Block = 256 threads handles a 32(t)x32(u)
// tile. Read phase: coalesced along t (q_id/resp are (U,T) row-major).
// Write phase: coalesced along u into (T,U)-layout d_sc/d_kcsc.
// ---------------------------------------------------------------------------
__global__ void __launch_bounds__(256) gather_kernel(
    const int* __restrict__ q_id, const int* __restrict__ resp,
    const float* __restrict__ dmu, const float* __restrict__ smu)
{
    __shared__ int sq[32][33];
    __shared__ int sr[32][33];

    const int t0 = blockIdx.x * 32;
    const int u0 = blockIdx.y * 32;
    const int w = threadIdx.x >> 5;
    const int lane = threadIdx.x & 31;

    // read: warp w covers u rows w*4..w*4+3, lanes sweep t
    #pragma unroll
    for (int rr = 0; rr < 4; rr++) {
        int ul = w * 4 + rr;
        int t = t0 + lane;
        if (t < T_DIM) {
            sq[ul][lane] = q_id[(u0 + ul) * T_DIM + t];
            sr[ul][lane] = resp[(u0 + ul) * T_DIM + t];
        }
    }
    __syncthreads();

    // write: warp w covers t rows w*4..w*4+3, lanes sweep u
    #pragma unroll
    for (int rr = 0; rr < 4; rr++) {
        int tl = w * 4 + rr;
        int t = t0 + tl;
        if (t < T_DIM) {
            int q = sq[lane][tl];
            int rs = sr[lane][tl];
            float2 mr = d_tab[2 * q + rs];
            int idx = t * U_DIM + u0 + lane;
            d_sc[idx] = make_float4(mr.x, mr.y, smu[q], dmu[q]);
            d_kcsc[idx] = d_kcq[q];
        }
    }
}

// ---------------------------------------------------------------------------
// Kernel C1: backward Kalman recursion. One warp per block, 32 users/warp,
// coalesced (T,U) reads/writes, fast reciprocal (b in (0,1) -> contractive,
// 2-ulp rcp error does not accumulate).
// ---------------------------------------------------------------------------
__global__ void __launch_bounds__(32) bwd_kernel()
{
    const int u = blockIdx.x * 32 + threadIdx.x;
    float b = 1.0f, c = 0.0f;
    #pragma unroll 4
    for (int t = T_DIM - 1; t >= 0; t--) {
        float4 f = d_sc[t * U_DIM + u];
        float bn = __fdividef(1.0f, 2.0f + f.y - b);
        c = bn * fmaf(f.y, f.x, c);
        b = bn;
        d_bc[t * U_DIM + u] = make_float4(b, c, f.z, f.w);
    }
}

// ---------------------------------------------------------------------------
// Kernel C2: forward scan with per-user KC state in shared memory.
// Layout curr[k*32+lane] -> bank-conflict-free for arbitrary per-lane kc.
// ---------------------------------------------------------------------------
__global__ void __launch_bounds__(32) fwd_kernel(float* __restrict__ out)
{
    const int lane = threadIdx.x;
    const int u = blockIdx.x * 32 + lane;

    __shared__ float curr[K_DIM * 32];
    #pragma unroll
    for (int k = 0; k < K_DIM; k++) curr[k * 32 + lane] = 0.0f;
    __syncwarp();

    #pragma unroll 4
    for (int t = 0; t < T_DIM; t++) {
        float4 f = d_bc[t * U_DIM + u];
        int kc = d_kcsc[t * U_DIM + u];
        float prev = curr[kc * 32 + lane];
        float m = fmaf(f.x, prev, f.y);
        curr[kc * 32 + lane] = m;
        out[u * T_DIM + t] = f.z * (m - f.w);   // ts * (ability - td)
    }

    // last_ability_kc: (U, K) appended after trial_logits
    float* o2 = out + (size_t)U_DIM * T_DIM + (size_t)u * K_DIM;
    #pragma unroll 4
    for (int k = 0; k < K_DIM; k++) o2[k] = curr[k * 32 + lane];
}

// ---------------------------------------------------------------------------
// Launch
// ---------------------------------------------------------------------------
extern "C" void kernel_launch(void* const* d_in, const int* in_sizes, int n_in,
                              void* d_out, int out_size)
{
    // metadata order: mask, q_id, kmap, resp, diff_mu, disc_mu, W1,b1,W2,b2,W3,b3
    const int* q_id = (const int*)d_in[1];
    const int* kmap = (const int*)d_in[2];
    const int* resp = (const int*)d_in[3];
    const float* dmu = (const float*)d_in[4];
    const float* smu = (const float*)d_in[5];
    const float* W1 = (const float*)d_in[6];
    const float* b1 = (const float*)d_in[7];
    const float* W2 = (const float*)d_in[8];
    const float* b2 = (const float*)d_in[9];
    const float* W3 = (const float*)d_in[10];
    const float* b3 = (const float*)d_in[11];
    float* out = (float*)d_out;

    mlp_table_kernel<<<625, 256>>>(dmu, smu, kmap, W1, b1, W2, b2, W3, b3);
    dim3 ggrid((T_DIM + 31) / 32, U_DIM / 32);
    gather_kernel<<<ggrid, 256>>>(q_id, resp, dmu, smu);
    bwd_kernel<<<U_DIM / 32, 32>>>();
    fwd_kernel<<<U_DIM / 32, 32>>>(out);
}

// round 8
// speedup vs baseline: 2.9524x; 2.9524x over previous
#include <cuda_runtime.h>
#include <cuda_bf16.h>
#include <math.h>

#define U_DIM 4096
#define T_DIM 200
#define K_DIM 64
#define Q_DIM 10000
#define H_DIM 128

typedef unsigned long long u64;

// Scratch (device globals; no allocation in kernel_launch)
__device__ float2 d_tab[2 * Q_DIM];              // (mu, r) per (q, resp)
__device__ unsigned char d_kcq[Q_DIM];           // kc per question
__device__ float2 d_mr[T_DIM * U_DIM];           // (mu, r) in (T,U) layout
__device__ float2 d_bc[T_DIM * U_DIM];           // (b, c) in (T,U) layout
__device__ float  d_ab[T_DIM * U_DIM];           // ability in (T,U) layout
__device__ unsigned char d_kcsc[T_DIM * U_DIM];  // kc in (T,U) layout

__device__ __forceinline__ float gelu_exact(float x) {
    return 0.5f * x * (1.0f + erff(x * 0.70710678118654752440f));
}

__device__ __forceinline__ u64 pack2(float lo, float hi) {
    u64 r; asm("mov.b64 %0, {%1, %2};" : "=l"(r) : "f"(lo), "f"(hi)); return r;
}
__device__ __forceinline__ void unpack2(u64 v, float& lo, float& hi) {
    asm("mov.b64 {%0, %1}, %2;" : "=f"(lo), "=f"(hi) : "l"(v));
}
__device__ __forceinline__ u64 fma2(u64 a, u64 b, u64 c) {
    u64 d; asm("fma.rn.f32x2 %0, %1, %2, %3;" : "=l"(d) : "l"(a), "l"(b), "l"(c));
    return d;
}

// ---------------------------------------------------------------------------
// Kernel A: per-(q,resp) MLP table + kc_of_q.
// One warp per 4 tasks (2 questions x resp {0,1}); layer-2 uses packed
// fma.rn.f32x2 (FFMA2) to halve FMA-pipe pressure. kmap is int32-bool.
// ---------------------------------------------------------------------------
__global__ void __launch_bounds__(256) mlp_table_kernel(
    const float* __restrict__ dmu, const float* __restrict__ smu,
    const int* __restrict__ kmap,
    const float* __restrict__ W1, const float* __restrict__ b1,
    const float* __restrict__ W2, const float* __restrict__ b2,
    const float* __restrict__ W3, const float* __restrict__ b3)
{
    for (int q = blockIdx.x * blockDim.x + threadIdx.x; q < Q_DIM;
         q += gridDim.x * blockDim.x) {
        int kc = 0;
        #pragma unroll 8
        for (int k = K_DIM - 1; k >= 0; k--) {
            if (kmap[q * K_DIM + k] != 0) kc = k;
        }
        d_kcq[q] = (unsigned char)kc;
    }

    const int lane = threadIdx.x & 31;
    const int gw = (blockIdx.x * blockDim.x + threadIdx.x) >> 5;
    if (gw >= Q_DIM / 2) return;
    const int q0 = gw * 2;

    const float x0a = dmu[q0],     x1a = smu[q0];
    const float x0b = dmu[q0 + 1], x1b = smu[q0 + 1];

    // ---- layer 1: units 4*lane..4*lane+3 ----
    const float4 w10 = *(const float4*)(W1 + 0 * H_DIM + 4 * lane);
    const float4 w11 = *(const float4*)(W1 + 1 * H_DIM + 4 * lane);
    const float4 w12 = *(const float4*)(W1 + 2 * H_DIM + 4 * lane);
    const float4 b1v = *(const float4*)(b1 + 4 * lane);
    float r0[4] = {w10.x, w10.y, w10.z, w10.w};
    float r1[4] = {w11.x, w11.y, w11.z, w11.w};
    float r2[4] = {w12.x, w12.y, w12.z, w12.w};
    float bb[4] = {b1v.x, b1v.y, b1v.z, b1v.w};

    float h[4][4];
    #pragma unroll
    for (int e = 0; e < 4; e++) {
        float ba  = fmaf(x0a, r0[e], fmaf(x1a, r1[e], bb[e]));
        float bbq = fmaf(x0b, r0[e], fmaf(x1b, r1[e], bb[e]));
        h[0][e] = gelu_exact(ba);
        h[1][e] = gelu_exact(ba + r2[e]);
        h[2][e] = gelu_exact(bbq);
        h[3][e] = gelu_exact(bbq + r2[e]);
    }

    // ---- layer 2: 128x128 dense, FFMA2 packed ----
    const float4 b2v = *(const float4*)(b2 + 4 * lane);
    u64 accp[4][2];
    #pragma unroll
    for (int t = 0; t < 4; t++) {
        accp[t][0] = pack2(b2v.x, b2v.y);
        accp[t][1] = pack2(b2v.z, b2v.w);
    }
    #pragma unroll 4
    for (int base = 0; base < 32; base++) {
        u64 w2p[4][2];
        #pragma unroll
        for (int ii = 0; ii < 4; ii++) {
            const ulonglong2 wv =
                *(const ulonglong2*)(W2 + (base * 4 + ii) * H_DIM + 4 * lane);
            w2p[ii][0] = wv.x;
            w2p[ii][1] = wv.y;
        }
        #pragma unroll
        for (int t = 0; t < 4; t++) {
            #pragma unroll
            for (int ii = 0; ii < 4; ii++) {
                float hv = __shfl_sync(0xFFFFFFFFu, h[t][ii], base);
                u64 hp = pack2(hv, hv);
                accp[t][0] = fma2(hp, w2p[ii][0], accp[t][0]);
                accp[t][1] = fma2(hp, w2p[ii][1], accp[t][1]);
            }
        }
    }
    float h2[4][4];
    #pragma unroll
    for (int t = 0; t < 4; t++) {
        float a0, a1, a2, a3;
        unpack2(accp[t][0], a0, a1);
        unpack2(accp[t][1], a2, a3);
        h2[t][0] = gelu_exact(a0);
        h2[t][1] = gelu_exact(a1);
        h2[t][2] = gelu_exact(a2);
        h2[t][3] = gelu_exact(a3);
    }

    // ---- layer 3: 128 -> 2, warp reduce ----
    const float4 w3a = *(const float4*)(W3 + 8 * lane);
    const float4 w3b = *(const float4*)(W3 + 8 * lane + 4);
    const float b30 = b3[0], b31 = b3[1];

    float o0[4], o1[4];
    #pragma unroll
    for (int t = 0; t < 4; t++) {
        o0[t] = fmaf(h2[t][0], w3a.x, fmaf(h2[t][1], w3a.z,
                fmaf(h2[t][2], w3b.x, h2[t][3] * w3b.z)));
        o1[t] = fmaf(h2[t][0], w3a.y, fmaf(h2[t][1], w3a.w,
                fmaf(h2[t][2], w3b.y, h2[t][3] * w3b.w)));
    }
    #pragma unroll
    for (int off = 16; off; off >>= 1) {
        #pragma unroll
        for (int t = 0; t < 4; t++) {
            o0[t] += __shfl_xor_sync(0xFFFFFFFFu, o0[t], off);
            o1[t] += __shfl_xor_sync(0xFFFFFFFFu, o1[t], off);
        }
    }
    if (lane == 0) {
        #pragma unroll
        for (int t = 0; t < 4; t++) {
            float mu = gelu_exact(o0[t] + b30);
            float lv = gelu_exact(o1[t] + b31);
            float s = fmaxf(expf(0.5f * lv), 1e-8f);
            float inv = 1.0f / s;
            d_tab[4 * gw + t] = make_float2(mu, inv * inv);
        }
    }
}

// ---------------------------------------------------------------------------
// Kernel B: tiled transpose gather. 32(t)x32(u) tile per 256-thread block.
// Coalesced reads of (U,T) q_id/resp, coalesced (T,U) writes of (mu,r)+kc.
// ---------------------------------------------------------------------------
__global__ void __launch_bounds__(256) gather_kernel(
    const int* __restrict__ q_id, const int* __restrict__ resp)
{
    __shared__ int sq[32][33];
    __shared__ int sr[32][33];

    const int t0 = blockIdx.x * 32;
    const int u0 = blockIdx.y * 32;
    const int w = threadIdx.x >> 5;
    const int lane = threadIdx.x & 31;

    #pragma unroll
    for (int rr = 0; rr < 4; rr++) {
        int ul = w * 4 + rr;
        int t = t0 + lane;
        if (t < T_DIM) {
            sq[ul][lane] = q_id[(u0 + ul) * T_DIM + t];
            sr[ul][lane] = resp[(u0 + ul) * T_DIM + t];
        }
    }
    __syncthreads();

    #pragma unroll
    for (int rr = 0; rr < 4; rr++) {
        int tl = w * 4 + rr;
        int t = t0 + tl;
        if (t < T_DIM) {
            int q = sq[lane][tl];
            int rs = sr[lane][tl];
            int idx = t * U_DIM + u0 + lane;
            d_mr[idx] = d_tab[2 * q + rs];
            d_kcsc[idx] = d_kcq[q];
        }
    }
}

// ---------------------------------------------------------------------------
// Kernel C1: backward Kalman recursion, software-pipelined in chunks of 8.
// Batch 8 independent coalesced loads, then 8 serial recursion steps, then
// 8 coalesced stores -> exposed L2 latency amortized 8x.
// ---------------------------------------------------------------------------
__global__ void __launch_bounds__(32) bwd_kernel()
{
    const int u = blockIdx.x * 32 + threadIdx.x;
    float b = 1.0f, c = 0.0f;
    for (int tc = T_DIM - 8; tc >= 0; tc -= 8) {
        float2 f[8];
        #pragma unroll
        for (int j = 0; j < 8; j++) f[j] = d_mr[(tc + j) * U_DIM + u];
        float2 st[8];
        #pragma unroll
        for (int j = 7; j >= 0; j--) {
            float bn = __fdividef(1.0f, 2.0f + f[j].y - b);
            c = bn * fmaf(f[j].y, f[j].x, c);
            b = bn;
            st[j] = make_float2(b, c);
        }
        #pragma unroll
        for (int j = 0; j < 8; j++) d_bc[(tc + j) * U_DIM + u] = st[j];
    }
}

// ---------------------------------------------------------------------------
// Kernel C2: forward scan, software-pipelined in chunks of 8. KC state in
// shared with curr[k*32+lane] (bank-conflict-free). Ability written to (T,U)
// scratch (coalesced); last_ability_kc written directly.
// ---------------------------------------------------------------------------
__global__ void __launch_bounds__(32) fwd_kernel(float* __restrict__ out)
{
    const int lane = threadIdx.x;
    const int u = blockIdx.x * 32 + lane;

    __shared__ float curr[K_DIM * 32];
    #pragma unroll
    for (int k = 0; k < K_DIM; k++) curr[k * 32 + lane] = 0.0f;
    __syncwarp();

    for (int tc = 0; tc < T_DIM; tc += 8) {
        float2 f[8];
        int kc[8];
        #pragma unroll
        for (int j = 0; j < 8; j++) {
            f[j] = d_bc[(tc + j) * U_DIM + u];
            kc[j] = d_kcsc[(tc + j) * U_DIM + u];
        }
        #pragma unroll
        for (int j = 0; j < 8; j++) {
            float prev = curr[kc[j] * 32 + lane];
            float m = fmaf(f[j].x, prev, f[j].y);
            curr[kc[j] * 32 + lane] = m;
            d_ab[(tc + j) * U_DIM + u] = m;
        }
    }

    // last_ability_kc: (U, K) appended after trial_logits
    float* o2 = out + (size_t)U_DIM * T_DIM + (size_t)u * K_DIM;
    #pragma unroll 4
    for (int k = 0; k < K_DIM; k++) o2[k] = curr[k * 32 + lane];
}

// ---------------------------------------------------------------------------
// Kernel D: final logits. Tile-transpose ability (T,U)->(U,T); q_id read
// coalesced in (U,T); ts/td via small L1-resident tables; out coalesced.
// ---------------------------------------------------------------------------
__global__ void __launch_bounds__(256) final_kernel(
    const int* __restrict__ q_id,
    const float* __restrict__ dmu, const float* __restrict__ smu,
    float* __restrict__ out)
{
    __shared__ float sa[32][33];

    const int t0 = blockIdx.x * 32;
    const int u0 = blockIdx.y * 32;
    const int w = threadIdx.x >> 5;
    const int lane = threadIdx.x & 31;

    #pragma unroll
    for (int rr = 0; rr < 4; rr++) {
        int tl = w * 4 + rr;
        if (t0 + tl < T_DIM)
            sa[tl][lane] = d_ab[(t0 + tl) * U_DIM + u0 + lane];
    }
    __syncthreads();

    #pragma unroll
    for (int rr = 0; rr < 4; rr++) {
        int ul = w * 4 + rr;
        int t = t0 + lane;
        if (t < T_DIM) {
            int q = q_id[(u0 + ul) * T_DIM + t];
            float m = sa[lane][ul];
            out[(u0 + ul) * T_DIM + t] = smu[q] * (m - dmu[q]);
        }
    }
}

// ---------------------------------------------------------------------------
// Launch
// ---------------------------------------------------------------------------
extern "C" void kernel_launch(void* const* d_in, const int* in_sizes, int n_in,
                              void* d_out, int out_size)
{
    // metadata order: mask, q_id, kmap, resp, diff_mu, disc_mu, W1,b1,W2,b2,W3,b3
    const int* q_id = (const int*)d_in[1];
    const int* kmap = (const int*)d_in[2];
    const int* resp = (const int*)d_in[3];
    const float* dmu = (const float*)d_in[4];
    const float* smu = (const float*)d_in[5];
    const float* W1 = (const float*)d_in[6];
    const float* b1 = (const float*)d_in[7];
    const float* W2 = (const float*)d_in[8];
    const float* b2 = (const float*)d_in[9];
    const float* W3 = (const float*)d_in[10];
    const float* b3 = (const float*)d_in[11];
    float* out = (float*)d_out;

    mlp_table_kernel<<<625, 256>>>(dmu, smu, kmap, W1, b1, W2, b2, W3, b3);
    dim3 ggrid((T_DIM + 31) / 32, U_DIM / 32);
    gather_kernel<<<ggrid, 256>>>(q_id, resp);
    bwd_kernel<<<U_DIM / 32, 32>>>();
    fwd_kernel<<<U_DIM / 32, 32>>>(out);
    final_kernel<<<ggrid, 256>>>(q_id, dmu, smu, out);
}

// round 10
// speedup vs baseline: 2.9922x; 1.0135x over previous
#include <cuda_runtime.h>
#include <cuda_bf16.h>
#include <math.h>

#define U_DIM 4096
#define T_DIM 200
#define K_DIM 64
#define Q_DIM 10000
#define H_DIM 128

typedef unsigned long long u64;

// Scratch (device globals; no allocation in kernel_launch)
__device__ float2 d_tab[2 * Q_DIM];              // (mu, r) per (q, resp)
__device__ unsigned char d_kcq[Q_DIM];           // kc per question
__device__ float2 d_mr[T_DIM * U_DIM];           // (mu, r) in (T,U) layout
__device__ float2 d_bc_ut[U_DIM * T_DIM];        // (b, c) in (U,T) layout
__device__ float  d_ab_ut[U_DIM * T_DIM];        // ability in (U,T) layout
__device__ unsigned char d_kc_ut[U_DIM * T_DIM]; // kc in (U,T) layout

__device__ __forceinline__ float gelu_exact(float x) {
    return 0.5f * x * (1.0f + erff(x * 0.70710678118654752440f));
}

__device__ __forceinline__ u64 pack2(float lo, float hi) {
    u64 r; asm("mov.b64 %0, {%1, %2};" : "=l"(r) : "f"(lo), "f"(hi)); return r;
}
__device__ __forceinline__ void unpack2(u64 v, float& lo, float& hi) {
    asm("mov.b64 {%0, %1}, %2;" : "=f"(lo), "=f"(hi) : "l"(v));
}
__device__ __forceinline__ u64 fma2(u64 a, u64 b, u64 c) {
    u64 d; asm("fma.rn.f32x2 %0, %1, %2, %3;" : "=l"(d) : "l"(a), "l"(b), "l"(c));
    return d;
}

// ---------------------------------------------------------------------------
// Kernel A: per-(q,resp) MLP table + kc_of_q. One warp per 4 tasks
// (2 questions x resp {0,1}); layer-2 uses packed fma.rn.f32x2.
// kmap is int32-upconverted bool: test != 0.
// ---------------------------------------------------------------------------
__global__ void __launch_bounds__(256) mlp_table_kernel(
    const float* __restrict__ dmu, const float* __restrict__ smu,
    const int* __restrict__ kmap,
    const float* __restrict__ W1, const float* __restrict__ b1,
    const float* __restrict__ W2, const float* __restrict__ b2,
    const float* __restrict__ W3, const float* __restrict__ b3)
{
    for (int q = blockIdx.x * blockDim.x + threadIdx.x; q < Q_DIM;
         q += gridDim.x * blockDim.x) {
        int kc = 0;
        #pragma unroll 8
        for (int k = K_DIM - 1; k >= 0; k--) {
            if (kmap[q * K_DIM + k] != 0) kc = k;
        }
        d_kcq[q] = (unsigned char)kc;
    }

    const int lane = threadIdx.x & 31;
    const int gw = (blockIdx.x * blockDim.x + threadIdx.x) >> 5;
    if (gw >= Q_DIM / 2) return;
    const int q0 = gw * 2;

    const float x0a = dmu[q0],     x1a = smu[q0];
    const float x0b = dmu[q0 + 1], x1b = smu[q0 + 1];

    // ---- layer 1: units 4*lane..4*lane+3 ----
    const float4 w10 = *(const float4*)(W1 + 0 * H_DIM + 4 * lane);
    const float4 w11 = *(const float4*)(W1 + 1 * H_DIM + 4 * lane);
    const float4 w12 = *(const float4*)(W1 + 2 * H_DIM + 4 * lane);
    const float4 b1v = *(const float4*)(b1 + 4 * lane);
    float r0[4] = {w10.x, w10.y, w10.z, w10.w};
    float r1[4] = {w11.x, w11.y, w11.z, w11.w};
    float r2[4] = {w12.x, w12.y, w12.z, w12.w};
    float bb[4] = {b1v.x, b1v.y, b1v.z, b1v.w};

    float h[4][4];
    #pragma unroll
    for (int e = 0; e < 4; e++) {
        float ba  = fmaf(x0a, r0[e], fmaf(x1a, r1[e], bb[e]));
        float bbq = fmaf(x0b, r0[e], fmaf(x1b, r1[e], bb[e]));
        h[0][e] = gelu_exact(ba);
        h[1][e] = gelu_exact(ba + r2[e]);
        h[2][e] = gelu_exact(bbq);
        h[3][e] = gelu_exact(bbq + r2[e]);
    }

    // ---- layer 2: 128x128 dense, FFMA2 packed ----
    const float4 b2v = *(const float4*)(b2 + 4 * lane);
    u64 accp[4][2];
    #pragma unroll
    for (int t = 0; t < 4; t++) {
        accp[t][0] = pack2(b2v.x, b2v.y);
        accp[t][1] = pack2(b2v.z, b2v.w);
    }
    #pragma unroll 4
    for (int base = 0; base < 32; base++) {
        u64 w2p[4][2];
        #pragma unroll
        for (int ii = 0; ii < 4; ii++) {
            const ulonglong2 wv =
                *(const ulonglong2*)(W2 + (base * 4 + ii) * H_DIM + 4 * lane);
            w2p[ii][0] = wv.x;
            w2p[ii][1] = wv.y;
        }
        #pragma unroll
        for (int t = 0; t < 4; t++) {
            #pragma unroll
            for (int ii = 0; ii < 4; ii++) {
                float hv = __shfl_sync(0xFFFFFFFFu, h[t][ii], base);
                u64 hp = pack2(hv, hv);
                accp[t][0] = fma2(hp, w2p[ii][0], accp[t][0]);
                accp[t][1] = fma2(hp, w2p[ii][1], accp[t][1]);
            }
        }
    }
    float h2[4][4];
    #pragma unroll
    for (int t = 0; t < 4; t++) {
        float a0, a1, a2, a3;
        unpack2(accp[t][0], a0, a1);
        unpack2(accp[t][1], a2, a3);
        h2[t][0] = gelu_exact(a0);
        h2[t][1] = gelu_exact(a1);
        h2[t][2] = gelu_exact(a2);
        h2[t][3] = gelu_exact(a3);
    }

    // ---- layer 3: 128 -> 2, warp reduce ----
    const float4 w3a = *(const float4*)(W3 + 8 * lane);
    const float4 w3b = *(const float4*)(W3 + 8 * lane + 4);
    const float b30 = b3[0], b31 = b3[1];

    float o0[4], o1[4];
    #pragma unroll
    for (int t = 0; t < 4; t++) {
        o0[t] = fmaf(h2[t][0], w3a.x, fmaf(h2[t][1], w3a.z,
                fmaf(h2[t][2], w3b.x, h2[t][3] * w3b.z)));
        o1[t] = fmaf(h2[t][0], w3a.y, fmaf(h2[t][1], w3a.w,
                fmaf(h2[t][2], w3b.y, h2[t][3] * w3b.w)));
    }
    #pragma unroll
    for (int off = 16; off; off >>= 1) {
        #pragma unroll
        for (int t = 0; t < 4; t++) {
            o0[t] += __shfl_xor_sync(0xFFFFFFFFu, o0[t], off);
            o1[t] += __shfl_xor_sync(0xFFFFFFFFu, o1[t], off);
        }
    }
    if (lane == 0) {
        #pragma unroll
        for (int t = 0; t < 4; t++) {
            float mu = gelu_exact(o0[t] + b30);
            float lv = gelu_exact(o1[t] + b31);
            float s = fmaxf(expf(0.5f * lv), 1e-8f);
            float inv = 1.0f / s;
            d_tab[4 * gw + t] = make_float2(mu, inv * inv);
        }
    }
}

// ---------------------------------------------------------------------------
// Kernel B: tiled transpose gather. 32(t)x32(u) tile per 256-thread block.
// Read phase (coalesced along t): also emits kc in (U,T) layout (coalesced).
// Write phase (coalesced along u): emits (mu,r) in (T,U) layout for bwd.
// ---------------------------------------------------------------------------
__global__ void __launch_bounds__(256) gather_kernel(
    const int* __restrict__ q_id, const int* __restrict__ resp)
{
    __shared__ int sq[32][33];
    __shared__ int sr[32][33];

    const int t0 = blockIdx.x * 32;
    const int u0 = blockIdx.y * 32;
    const int w = threadIdx.x >> 5;
    const int lane = threadIdx.x & 31;

    #pragma unroll
    for (int rr = 0; rr < 4; rr++) {
        int ul = w * 4 + rr;
        int t = t0 + lane;
        if (t < T_DIM) {
            int q = q_id[(u0 + ul) * T_DIM + t];
            sq[ul][lane] = q;
            sr[ul][lane] = resp[(u0 + ul) * T_DIM + t];
            d_kc_ut[(u0 + ul) * T_DIM + t] = d_kcq[q];
        }
    }
    __syncthreads();

    #pragma unroll
    for (int rr = 0; rr < 4; rr++) {
        int tl = w * 4 + rr;
        int t = t0 + tl;
        if (t < T_DIM) {
            int q = sq[lane][tl];
            int rs = sr[lane][tl];
            d_mr[t * U_DIM + u0 + lane] = d_tab[2 * q + rs];
        }
    }
}

// ---------------------------------------------------------------------------
// Kernel C1: backward Kalman recursion, software-pipelined in chunks of 8.
// Loads coalesced from (T,U) d_mr; stores per-thread-contiguous (U,T) float4s
// so the forward kernel can read fully coalesced.
// ---------------------------------------------------------------------------
__global__ void __launch_bounds__(32) bwd_kernel()
{
    const int u = blockIdx.x * 32 + threadIdx.x;
    float b = 1.0f, c = 0.0f;
    for (int tc = T_DIM - 8; tc >= 0; tc -= 8) {
        float2 f[8];
        #pragma unroll
        for (int j = 0; j < 8; j++) f[j] = d_mr[(tc + j) * U_DIM + u];
        float2 st[8];
        #pragma unroll
        for (int j = 7; j >= 0; j--) {
            float bn = __fdividef(1.0f, 2.0f + f[j].y - b);
            c = bn * fmaf(f[j].y, f[j].x, c);
            b = bn;
            st[j] = make_float2(b, c);
        }
        // 4 x float4 to thread-contiguous (U,T) region (16B-aligned: index even)
        float4* dst = (float4*)&d_bc_ut[u * T_DIM + tc];
        #pragma unroll
        for (int j = 0; j < 4; j++)
            dst[j] = make_float4(st[2 * j].x, st[2 * j].y,
                                 st[2 * j + 1].x, st[2 * j + 1].y);
    }
}

// ---------------------------------------------------------------------------
// Kernel C2: forward scan, WARP-PER-USER with register-resident KC state.
// Lane (kc&31) owns kc's state: s0 for kc<32, s1 for kc>=32. Per trial,
// (b,c,kc) broadcast via shfl from the lane that loaded it (coalesced chunk
// loads); owner lane does one FFMA and buffers m; chunk end flushes 128B
// coalesced to (U,T) ability scratch. 4096 warps -> ~27/SM: issue-bound.
// ---------------------------------------------------------------------------
__global__ void __launch_bounds__(256) fwd_kernel(float* __restrict__ out)
{
    const int lane = threadIdx.x & 31;
    const int wid = threadIdx.x >> 5;
    const int u = blockIdx.x * 8 + wid;

    __shared__ float sbuf[8][32];
    float s0 = 0.0f, s1 = 0.0f;

    // 6 full chunks of 32
    for (int tc = 0; tc < 192; tc += 32) {
        float2 bc = d_bc_ut[u * T_DIM + tc + lane];
        int kc = d_kc_ut[u * T_DIM + tc + lane];
        #pragma unroll
        for (int j = 0; j < 32; j++) {
            float bj = __shfl_sync(0xFFFFFFFFu, bc.x, j);
            float cj = __shfl_sync(0xFFFFFFFFu, bc.y, j);
            int   kj = __shfl_sync(0xFFFFFFFFu, kc, j);
            if ((kj & 31) == lane) {
                float s = (kj & 32) ? s1 : s0;
                float m = fmaf(bj, s, cj);
                if (kj & 32) s1 = m; else s0 = m;
                sbuf[wid][j] = m;
            }
        }
        __syncwarp();
        d_ab_ut[u * T_DIM + tc + lane] = sbuf[wid][lane];
        __syncwarp();
    }
    // tail chunk: t = 192..199 (8 trials)
    {
        const int tc = 192;
        float2 bc = make_float2(0.0f, 0.0f);
        int kc = 0;
        if (lane < 8) {
            bc = d_bc_ut[u * T_DIM + tc + lane];
            kc = d_kc_ut[u * T_DIM + tc + lane];
        }
        #pragma unroll
        for (int j = 0; j < 8; j++) {
            float bj = __shfl_sync(0xFFFFFFFFu, bc.x, j);
            float cj = __shfl_sync(0xFFFFFFFFu, bc.y, j);
            int   kj = __shfl_sync(0xFFFFFFFFu, kc, j);
            if ((kj & 31) == lane) {
                float s = (kj & 32) ? s1 : s0;
                float m = fmaf(bj, s, cj);
                if (kj & 32) s1 = m; else s0 = m;
                sbuf[wid][j] = m;
            }
        }
        __syncwarp();
        if (lane < 8) d_ab_ut[u * T_DIM + tc + lane] = sbuf[wid][lane];
    }

    // last_ability_kc: (U, K); lane owns k=lane (s0) and k=lane+32 (s1)
    float* o2 = out + (size_t)U_DIM * T_DIM + (size_t)u * K_DIM;
    o2[lane] = s0;
    o2[32 + lane] = s1;
}

// ---------------------------------------------------------------------------
// Kernel D: final logits — pure elementwise in (U,T): all accesses coalesced
// (smu/dmu are small L1-resident gather tables).
// ---------------------------------------------------------------------------
__global__ void __launch_bounds__(256) final_kernel(
    const int* __restrict__ q_id,
    const float* __restrict__ dmu, const float* __restrict__ smu,
    float* __restrict__ out)
{
    int idx = blockIdx.x * blockDim.x + threadIdx.x;
    if (idx >= U_DIM * T_DIM) return;
    int q = q_id[idx];
    out[idx] = smu[q] * (d_ab_ut[idx] - dmu[q]);
}

// ---------------------------------------------------------------------------
// Launch
// ---------------------------------------------------------------------------
extern "C" void kernel_launch(void* const* d_in, const int* in_sizes, int n_in,
                              void* d_out, int out_size)
{
    // metadata order: mask, q_id, kmap, resp, diff_mu, disc_mu, W1,b1,W2,b2,W3,b3
    const int* q_id = (const int*)d_in[1];
    const int* kmap = (const int*)d_in[2];
    const int* resp = (const int*)d_in[3];
    const float* dmu = (const float*)d_in[4];
    const float* smu = (const float*)d_in[5];
    const float* W1 = (const float*)d_in[6];
    const float* b1 = (const float*)d_in[7];
    const float* W2 = (const float*)d_in[8];
    const float* b2 = (const float*)d_in[9];
    const float* W3 = (const float*)d_in[10];
    const float* b3 = (const float*)d_in[11];
    float* out = (float*)d_out;

    mlp_table_kernel<<<625, 256>>>(dmu, smu, kmap, W1, b1, W2, b2, W3, b3);
    dim3 ggrid((T_DIM + 31) / 32, U_DIM / 32);
    gather_kernel<<<ggrid, 256>>>(q_id, resp);
    bwd_kernel<<<U_DIM / 32, 32>>>();
    fwd_kernel<<<U_DIM / 8, 256>>>(out);
    final_kernel<<<(U_DIM * T_DIM + 255) / 256, 256>>>(q_id, dmu, smu, out);
}

// round 11
// speedup vs baseline: 3.9113x; 1.3072x over previous
#include <cuda_runtime.h>
#include <cuda_bf16.h>
#include <math.h>

#define U_DIM 4096
#define T_DIM 200
#define K_DIM 64
#define Q_DIM 10000
#define H_DIM 128

typedef unsigned long long u64;

// Scratch (device globals; no allocation in kernel_launch)
__device__ float2 d_tab[2 * Q_DIM];              // (mu, r) per (q, resp)
__device__ unsigned char d_kcq[Q_DIM];           // kc per question
__device__ float2 d_bc_ut[U_DIM * T_DIM];        // (b, c) in (U,T) layout

__device__ __forceinline__ float gelu_exact(float x) {
    return 0.5f * x * (1.0f + erff(x * 0.70710678118654752440f));
}

__device__ __forceinline__ u64 pack2(float lo, float hi) {
    u64 r; asm("mov.b64 %0, {%1, %2};" : "=l"(r) : "f"(lo), "f"(hi)); return r;
}
__device__ __forceinline__ void unpack2(u64 v, float& lo, float& hi) {
    asm("mov.b64 {%0, %1}, %2;" : "=f"(lo), "=f"(hi) : "l"(v));
}
__device__ __forceinline__ u64 fma2(u64 a, u64 b, u64 c) {
    u64 d; asm("fma.rn.f32x2 %0, %1, %2, %3;" : "=l"(d) : "l"(a), "l"(b), "l"(c));
    return d;
}

// ---------------------------------------------------------------------------
// Kernel A: per-(q,resp) MLP table + kc_of_q. One warp per 4 tasks
// (2 questions x resp {0,1}); layer-2 uses packed fma.rn.f32x2.
// kmap is int32-upconverted bool: test != 0.
// ---------------------------------------------------------------------------
__global__ void __launch_bounds__(256) mlp_table_kernel(
    const float* __restrict__ dmu, const float* __restrict__ smu,
    const int* __restrict__ kmap,
    const float* __restrict__ W1, const float* __restrict__ b1,
    const float* __restrict__ W2, const float* __restrict__ b2,
    const float* __restrict__ W3, const float* __restrict__ b3)
{
    for (int q = blockIdx.x * blockDim.x + threadIdx.x; q < Q_DIM;
         q += gridDim.x * blockDim.x) {
        int kc = 0;
        #pragma unroll 8
        for (int k = K_DIM - 1; k >= 0; k--) {
            if (kmap[q * K_DIM + k] != 0) kc = k;
        }
        d_kcq[q] = (unsigned char)kc;
    }

    const int lane = threadIdx.x & 31;
    const int gw = (blockIdx.x * blockDim.x + threadIdx.x) >> 5;
    if (gw >= Q_DIM / 2) return;
    const int q0 = gw * 2;

    const float x0a = dmu[q0],     x1a = smu[q0];
    const float x0b = dmu[q0 + 1], x1b = smu[q0 + 1];

    // ---- layer 1: units 4*lane..4*lane+3 ----
    const float4 w10 = *(const float4*)(W1 + 0 * H_DIM + 4 * lane);
    const float4 w11 = *(const float4*)(W1 + 1 * H_DIM + 4 * lane);
    const float4 w12 = *(const float4*)(W1 + 2 * H_DIM + 4 * lane);
    const float4 b1v = *(const float4*)(b1 + 4 * lane);
    float r0[4] = {w10.x, w10.y, w10.z, w10.w};
    float r1[4] = {w11.x, w11.y, w11.z, w11.w};
    float r2[4] = {w12.x, w12.y, w12.z, w12.w};
    float bb[4] = {b1v.x, b1v.y, b1v.z, b1v.w};

    float h[4][4];
    #pragma unroll
    for (int e = 0; e < 4; e++) {
        float ba  = fmaf(x0a, r0[e], fmaf(x1a, r1[e], bb[e]));
        float bbq = fmaf(x0b, r0[e], fmaf(x1b, r1[e], bb[e]));
        h[0][e] = gelu_exact(ba);
        h[1][e] = gelu_exact(ba + r2[e]);
        h[2][e] = gelu_exact(bbq);
        h[3][e] = gelu_exact(bbq + r2[e]);
    }

    // ---- layer 2: 128x128 dense, FFMA2 packed ----
    const float4 b2v = *(const float4*)(b2 + 4 * lane);
    u64 accp[4][2];
    #pragma unroll
    for (int t = 0; t < 4; t++) {
        accp[t][0] = pack2(b2v.x, b2v.y);
        accp[t][1] = pack2(b2v.z, b2v.w);
    }
    #pragma unroll 4
    for (int base = 0; base < 32; base++) {
        u64 w2p[4][2];
        #pragma unroll
        for (int ii = 0; ii < 4; ii++) {
            const ulonglong2 wv =
                *(const ulonglong2*)(W2 + (base * 4 + ii) * H_DIM + 4 * lane);
            w2p[ii][0] = wv.x;
            w2p[ii][1] = wv.y;
        }
        #pragma unroll
        for (int t = 0; t < 4; t++) {
            #pragma unroll
            for (int ii = 0; ii < 4; ii++) {
                float hv = __shfl_sync(0xFFFFFFFFu, h[t][ii], base);
                u64 hp = pack2(hv, hv);
                accp[t][0] = fma2(hp, w2p[ii][0], accp[t][0]);
                accp[t][1] = fma2(hp, w2p[ii][1], accp[t][1]);
            }
        }
    }
    float h2[4][4];
    #pragma unroll
    for (int t = 0; t < 4; t++) {
        float a0, a1, a2, a3;
        unpack2(accp[t][0], a0, a1);
        unpack2(accp[t][1], a2, a3);
        h2[t][0] = gelu_exact(a0);
        h2[t][1] = gelu_exact(a1);
        h2[t][2] = gelu_exact(a2);
        h2[t][3] = gelu_exact(a3);
    }

    // ---- layer 3: 128 -> 2, warp reduce ----
    const float4 w3a = *(const float4*)(W3 + 8 * lane);
    const float4 w3b = *(const float4*)(W3 + 8 * lane + 4);
    const float b30 = b3[0], b31 = b3[1];

    float o0[4], o1[4];
    #pragma unroll
    for (int t = 0; t < 4; t++) {
        o0[t] = fmaf(h2[t][0], w3a.x, fmaf(h2[t][1], w3a.z,
                fmaf(h2[t][2], w3b.x, h2[t][3] * w3b.z)));
        o1[t] = fmaf(h2[t][0], w3a.y, fmaf(h2[t][1], w3a.w,
                fmaf(h2[t][2], w3b.y, h2[t][3] * w3b.w)));
    }
    #pragma unroll
    for (int off = 16; off; off >>= 1) {
        #pragma unroll
        for (int t = 0; t < 4; t++) {
            o0[t] += __shfl_xor_sync(0xFFFFFFFFu, o0[t], off);
            o1[t] += __shfl_xor_sync(0xFFFFFFFFu, o1[t], off);
        }
    }
    if (lane == 0) {
        #pragma unroll
        for (int t = 0; t < 4; t++) {
            float mu = gelu_exact(o0[t] + b30);
            float lv = gelu_exact(o1[t] + b31);
            float s = fmaxf(expf(0.5f * lv), 1e-8f);
            float inv = 1.0f / s;
            d_tab[4 * gw + t] = make_float2(mu, inv * inv);
        }
    }
}

// ---------------------------------------------------------------------------
// Kernel B: backward Kalman recursion as a WARP-PARALLEL MOBIUS SCAN.
// Step t is linear on homogeneous (p,q,w) [b=p/q, c=w/q]:
//   M_t = [[0,1,0],[-1,a,0],[0,g,1]], a=2+r_t, g=r_t*mu_t; v_t = M_t v_{t+1}.
// Lane l owns t in [7l, 7l+7) (t>=200 -> identity). Build local product,
// Kogge-Stone inclusive SUFFIX scan of 3x3 matrices (3rd col (0,0,m22)),
// renormalized per combine (uniform scaling preserves ratios; q>0 always),
// exclusive shift gives the carry; local scalar replay emits (b,c) per t.
// 4096 warps -> issue-bound, all loads/stores lane-contiguous.
// ---------------------------------------------------------------------------
__global__ void __launch_bounds__(256) bwd_scan_kernel(
    const int* __restrict__ q_id, const int* __restrict__ resp)
{
    const int lane = threadIdx.x & 31;
    const int wid  = threadIdx.x >> 5;
    const int u = blockIdx.x * 8 + wid;
    const int base = lane * 7;

    // load segment inputs (L1 catches the 800B/warp row overlap)
    float mu[7], rr[7];
    #pragma unroll
    for (int j = 0; j < 7; j++) {
        int t = base + j;
        if (t < T_DIM) {
            int q  = q_id[u * T_DIM + t];
            int rs = resp[u * T_DIM + t];
            float2 f = d_tab[2 * q + rs];
            mu[j] = f.x; rr[j] = f.y;
        } else { mu[j] = 0.0f; rr[j] = 0.0f; }
    }

    // local product S = M_base * ... * M_{base+6}
    float m00 = 1.0f, m01 = 0.0f, m10 = 0.0f, m11 = 1.0f;
    float m20 = 0.0f, m21 = 0.0f, m22 = 1.0f;
    #pragma unroll
    for (int j = 6; j >= 0; j--) {
        if (base + j < T_DIM) {
            float a = 2.0f + rr[j];
            float g = rr[j] * mu[j];
            float n00 = m10,                  n01 = m11;
            float n10 = fmaf(a, m10, -m00);   n10 = n10;
            float n11 = fmaf(a, m11, -m01);
            float n20 = fmaf(g, m10, m20);
            float n21 = fmaf(g, m11, m21);
            m00 = n00; m01 = n01; m10 = n10; m11 = n11;
            m20 = n20; m21 = n21;  // m22 unchanged
        }
    }

    // inclusive suffix scan: T_l = S_l * S_{l+1} * ... * S_31
    #pragma unroll
    for (int d = 1; d < 32; d <<= 1) {
        float b00 = __shfl_down_sync(0xFFFFFFFFu, m00, d);
        float b01 = __shfl_down_sync(0xFFFFFFFFu, m01, d);
        float b10 = __shfl_down_sync(0xFFFFFFFFu, m10, d);
        float b11 = __shfl_down_sync(0xFFFFFFFFu, m11, d);
        float b20 = __shfl_down_sync(0xFFFFFFFFu, m20, d);
        float b21 = __shfl_down_sync(0xFFFFFFFFu, m21, d);
        float b22 = __shfl_down_sync(0xFFFFFFFFu, m22, d);
        if (lane + d < 32) {
            float c00 = fmaf(m00, b00, m01 * b10);
            float c01 = fmaf(m00, b01, m01 * b11);
            float c10 = fmaf(m10, b00, m11 * b10);
            float c11 = fmaf(m10, b01, m11 * b11);
            float c20 = fmaf(m20, b00, fmaf(m21, b10, m22 * b20));
            float c21 = fmaf(m20, b01, fmaf(m21, b11, m22 * b21));
            float c22 = m22 * b22;
            float s = __fdividef(1.0f, fabsf(c10) + fabsf(c11) + 1e-30f);
            m00 = c00 * s; m01 = c01 * s;
            m10 = c10 * s; m11 = c11 * s;
            m20 = c20 * s; m21 = c21 * s; m22 = c22 * s;
        }
    }

    // exclusive: P_l = T_{l+1}; lane 31 -> identity
    float p00 = __shfl_down_sync(0xFFFFFFFFu, m00, 1);
    float p01 = __shfl_down_sync(0xFFFFFFFFu, m01, 1);
    float p10 = __shfl_down_sync(0xFFFFFFFFu, m10, 1);
    float p11 = __shfl_down_sync(0xFFFFFFFFu, m11, 1);
    float p20 = __shfl_down_sync(0xFFFFFFFFu, m20, 1);
    float p21 = __shfl_down_sync(0xFFFFFFFFu, m21, 1);
    if (lane == 31) {
        p00 = 1.0f; p01 = 0.0f; p10 = 0.0f; p11 = 1.0f; p20 = 0.0f; p21 = 0.0f;
    }

    // carry state v = P * (1,1,0)^T  ->  b = p/q, c = w/q   (q > 0 invariant)
    float pp = p00 + p01;
    float qq = p10 + p11;
    float ww = p20 + p21;
    float invq = __fdividef(1.0f, qq);
    float b = pp * invq;
    float c = ww * invq;

    // local replay (exact reference arithmetic from the carry), then store
    float2 st[7];
    #pragma unroll
    for (int j = 6; j >= 0; j--) {
        if (base + j < T_DIM) {
            float bn = __fdividef(1.0f, 2.0f + rr[j] - b);
            c = bn * fmaf(rr[j], mu[j], c);
            b = bn;
            st[j] = make_float2(b, c);
        }
    }
    #pragma unroll
    for (int j = 0; j < 7; j++) {
        int t = base + j;
        if (t < T_DIM) d_bc_ut[u * T_DIM + t] = st[j];
    }
}

// ---------------------------------------------------------------------------
// Kernel C: forward scan, WARP-PER-USER with register-resident KC state.
// Lane (kc&31) owns kc's state (s0: kc<32, s1: kc>=32). Per trial, (b,c,kc)
// broadcast via shfl from the lane that loaded it; owner lane does one FFMA
// and buffers m. Chunk end: compute logits DIRECTLY (q already in-register,
// smu/dmu are L1-hot tables) and store coalesced -> no ability scratch, no
// final kernel. last_ability stored from registers at the end.
// ---------------------------------------------------------------------------
__global__ void __launch_bounds__(256) fwd_kernel(
    const int* __restrict__ q_id,
    const float* __restrict__ dmu, const float* __restrict__ smu,
    float* __restrict__ out)
{
    const int lane = threadIdx.x & 31;
    const int wid = threadIdx.x >> 5;
    const int u = blockIdx.x * 8 + wid;

    __shared__ float sbuf[8][32];
    float s0 = 0.0f, s1 = 0.0f;

    // 6 full chunks of 32
    for (int tc = 0; tc < 192; tc += 32) {
        float2 bc = d_bc_ut[u * T_DIM + tc + lane];
        int q = q_id[u * T_DIM + tc + lane];
        int kc = d_kcq[q];
        #pragma unroll
        for (int j = 0; j < 32; j++) {
            float bj = __shfl_sync(0xFFFFFFFFu, bc.x, j);
            float cj = __shfl_sync(0xFFFFFFFFu, bc.y, j);
            int   kj = __shfl_sync(0xFFFFFFFFu, kc, j);
            if ((kj & 31) == lane) {
                float s = (kj & 32) ? s1 : s0;
                float m = fmaf(bj, s, cj);
                if (kj & 32) s1 = m; else s0 = m;
                sbuf[wid][j] = m;
            }
        }
        __syncwarp();
        float m = sbuf[wid][lane];
        out[u * T_DIM + tc + lane] = smu[q] * (m - dmu[q]);
        __syncwarp();
    }
    // tail chunk: t = 192..199
    {
        const int tc = 192;
        float2 bc = make_float2(0.0f, 0.0f);
        int q = 0, kc = 0;
        if (lane < 8) {
            bc = d_bc_ut[u * T_DIM + tc + lane];
            q = q_id[u * T_DIM + tc + lane];
            kc = d_kcq[q];
        }
        #pragma unroll
        for (int j = 0; j < 8; j++) {
            float bj = __shfl_sync(0xFFFFFFFFu, bc.x, j);
            float cj = __shfl_sync(0xFFFFFFFFu, bc.y, j);
            int   kj = __shfl_sync(0xFFFFFFFFu, kc, j);
            if ((kj & 31) == lane) {
                float s = (kj & 32) ? s1 : s0;
                float m = fmaf(bj, s, cj);
                if (kj & 32) s1 = m; else s0 = m;
                sbuf[wid][j] = m;
            }
        }
        __syncwarp();
        if (lane < 8) {
            float m = sbuf[wid][lane];
            out[u * T_DIM + tc + lane] = smu[q] * (m - dmu[q]);
        }
    }

    // last_ability_kc: (U, K); lane owns k=lane (s0) and k=lane+32 (s1)
    float* o2 = out + (size_t)U_DIM * T_DIM + (size_t)u * K_DIM;
    o2[lane] = s0;
    o2[32 + lane] = s1;
}

// ---------------------------------------------------------------------------
// Launch
// ---------------------------------------------------------------------------
extern "C" void kernel_launch(void* const* d_in, const int* in_sizes, int n_in,
                              void* d_out, int out_size)
{
    // metadata order: mask, q_id, kmap, resp, diff_mu, disc_mu, W1,b1,W2,b2,W3,b3
    const int* q_id = (const int*)d_in[1];
    const int* kmap = (const int*)d_in[2];
    const int* resp = (const int*)d_in[3];
    const float* dmu = (const float*)d_in[4];
    const float* smu = (const float*)d_in[5];
    const float* W1 = (const float*)d_in[6];
    const float* b1 = (const float*)d_in[7];
    const float* W2 = (const float*)d_in[8];
    const float* b2 = (const float*)d_in[9];
    const float* W3 = (const float*)d_in[10];
    const float* b3 = (const float*)d_in[11];
    float* out = (float*)d_out;

    mlp_table_kernel<<<625, 256>>>(dmu, smu, kmap, W1, b1, W2, b2, W3, b3);
    bwd_scan_kernel<<<U_DIM / 8, 256>>>(q_id, resp);
    fwd_kernel<<<U_DIM / 8, 256>>>(q_id, dmu, smu, out);
}

// round 12
// speedup vs baseline: 4.0342x; 1.0314x over previous
#include <cuda_runtime.h>
#include <cuda_bf16.h>
#include <math.h>

#define U_DIM 4096
#define T_DIM 200
#define K_DIM 64
#define Q_DIM 10000
#define H_DIM 128

typedef unsigned long long u64;

// Scratch (device globals; no allocation in kernel_launch)
__device__ float2 d_tab[2 * Q_DIM];              // (mu, r) per (q, resp)
__device__ unsigned char d_kcq[Q_DIM];           // kc per question

__device__ __forceinline__ float gelu_exact(float x) {
    return 0.5f * x * (1.0f + erff(x * 0.70710678118654752440f));
}

__device__ __forceinline__ u64 pack2(float lo, float hi) {
    u64 r; asm("mov.b64 %0, {%1, %2};" : "=l"(r) : "f"(lo), "f"(hi)); return r;
}
__device__ __forceinline__ void unpack2(u64 v, float& lo, float& hi) {
    asm("mov.b64 {%0, %1}, %2;" : "=f"(lo), "=f"(hi) : "l"(v));
}
__device__ __forceinline__ u64 fma2(u64 a, u64 b, u64 c) {
    u64 d; asm("fma.rn.f32x2 %0, %1, %2, %3;" : "=l"(d) : "l"(a), "l"(b), "l"(c));
    return d;
}

// ---------------------------------------------------------------------------
// Kernel A: per-(q,resp) MLP table + kc_of_q.
// One warp per 8 tasks (4 questions x resp {0,1}) -> W2 L1 traffic per task
// HALVED vs 4-task version (L1 was the binding pipe at 60%).
// kc_of_q: the same warp handles its own 4 questions with 2 coalesced loads
// + 2 ballots each (replaces 64-iter scattered loop).
// kmap is int32-upconverted bool: test != 0.
// ---------------------------------------------------------------------------
__global__ void __launch_bounds__(256) mlp_table_kernel(
    const float* __restrict__ dmu, const float* __restrict__ smu,
    const int* __restrict__ kmap,
    const float* __restrict__ W1, const float* __restrict__ b1,
    const float* __restrict__ W2, const float* __restrict__ b2,
    const float* __restrict__ W3, const float* __restrict__ b3)
{
    const int lane = threadIdx.x & 31;
    const int gw = (blockIdx.x * blockDim.x + threadIdx.x) >> 5;
    if (gw >= Q_DIM / 4) return;
    const int q0 = gw * 4;

    // ---- kc_of_q via ballot: warp owns questions q0..q0+3 ----
    #pragma unroll
    for (int j = 0; j < 4; j++) {
        int q = q0 + j;
        int vlo = kmap[q * K_DIM + lane];
        int vhi = kmap[q * K_DIM + 32 + lane];
        unsigned lo = __ballot_sync(0xFFFFFFFFu, vlo != 0);
        unsigned hi = __ballot_sync(0xFFFFFFFFu, vhi != 0);
        if (lane == 0) {
            int kc = lo ? (__ffs(lo) - 1) : (32 + __ffs(hi) - 1);
            d_kcq[q] = (unsigned char)kc;
        }
    }

    float x0[4], x1[4];
    #pragma unroll
    for (int j = 0; j < 4; j++) { x0[j] = dmu[q0 + j]; x1[j] = smu[q0 + j]; }

    // ---- layer 1: units 4*lane..4*lane+3; tasks tt: q = q0+(tt>>1)... ----
    // task tt in [0,8): question j = tt>>1, resp = tt&1
    const float4 w10 = *(const float4*)(W1 + 0 * H_DIM + 4 * lane);
    const float4 w11 = *(const float4*)(W1 + 1 * H_DIM + 4 * lane);
    const float4 w12 = *(const float4*)(W1 + 2 * H_DIM + 4 * lane);
    const float4 b1v = *(const float4*)(b1 + 4 * lane);
    float r0[4] = {w10.x, w10.y, w10.z, w10.w};
    float r1[4] = {w11.x, w11.y, w11.z, w11.w};
    float r2[4] = {w12.x, w12.y, w12.z, w12.w};
    float bb[4] = {b1v.x, b1v.y, b1v.z, b1v.w};

    float h[8][4];
    #pragma unroll
    for (int j = 0; j < 4; j++) {
        #pragma unroll
        for (int e = 0; e < 4; e++) {
            float pre = fmaf(x0[j], r0[e], fmaf(x1[j], r1[e], bb[e]));
            h[2 * j][e]     = gelu_exact(pre);
            h[2 * j + 1][e] = gelu_exact(pre + r2[e]);
        }
    }

    // ---- layer 2: 128x128 dense, FFMA2 packed, 8 accumulator sets ----
    const float4 b2v = *(const float4*)(b2 + 4 * lane);
    u64 accp[8][2];
    #pragma unroll
    for (int t = 0; t < 8; t++) {
        accp[t][0] = pack2(b2v.x, b2v.y);
        accp[t][1] = pack2(b2v.z, b2v.w);
    }
    #pragma unroll 2
    for (int base = 0; base < 32; base++) {
        u64 w2p[4][2];
        #pragma unroll
        for (int ii = 0; ii < 4; ii++) {
            const ulonglong2 wv =
                *(const ulonglong2*)(W2 + (base * 4 + ii) * H_DIM + 4 * lane);
            w2p[ii][0] = wv.x;
            w2p[ii][1] = wv.y;
        }
        #pragma unroll
        for (int t = 0; t < 8; t++) {
            #pragma unroll
            for (int ii = 0; ii < 4; ii++) {
                float hv = __shfl_sync(0xFFFFFFFFu, h[t][ii], base);
                u64 hp = pack2(hv, hv);
                accp[t][0] = fma2(hp, w2p[ii][0], accp[t][0]);
                accp[t][1] = fma2(hp, w2p[ii][1], accp[t][1]);
            }
        }
    }
    float h2[8][4];
    #pragma unroll
    for (int t = 0; t < 8; t++) {
        float a0, a1, a2, a3;
        unpack2(accp[t][0], a0, a1);
        unpack2(accp[t][1], a2, a3);
        h2[t][0] = gelu_exact(a0);
        h2[t][1] = gelu_exact(a1);
        h2[t][2] = gelu_exact(a2);
        h2[t][3] = gelu_exact(a3);
    }

    // ---- layer 3: 128 -> 2, warp reduce ----
    const float4 w3a = *(const float4*)(W3 + 8 * lane);
    const float4 w3b = *(const float4*)(W3 + 8 * lane + 4);
    const float b30 = b3[0], b31 = b3[1];

    float o0[8], o1[8];
    #pragma unroll
    for (int t = 0; t < 8; t++) {
        o0[t] = fmaf(h2[t][0], w3a.x, fmaf(h2[t][1], w3a.z,
                fmaf(h2[t][2], w3b.x, h2[t][3] * w3b.z)));
        o1[t] = fmaf(h2[t][0], w3a.y, fmaf(h2[t][1], w3a.w,
                fmaf(h2[t][2], w3b.y, h2[t][3] * w3b.w)));
    }
    #pragma unroll
    for (int off = 16; off; off >>= 1) {
        #pragma unroll
        for (int t = 0; t < 8; t++) {
            o0[t] += __shfl_xor_sync(0xFFFFFFFFu, o0[t], off);
            o1[t] += __shfl_xor_sync(0xFFFFFFFFu, o1[t], off);
        }
    }
    if (lane == 0) {
        #pragma unroll
        for (int t = 0; t < 8; t++) {
            float mu = gelu_exact(o0[t] + b30);
            float lv = gelu_exact(o1[t] + b31);
            float s = fmaxf(expf(0.5f * lv), 1e-8f);
            float inv = 1.0f / s;
            d_tab[8 * gw + t] = make_float2(mu, inv * inv);
        }
    }
}

// ---------------------------------------------------------------------------
// Kernel B: FUSED backward Mobius scan + forward KC scan, warp-per-user.
// Backward: step t is linear on homogeneous (p,q,w) [b=p/q, c=w/q]:
//   M_t = [[0,1,0],[-1,a,0],[0,g,1]], a=2+r_t, g=r_t*mu_t. Lane l owns
//   t in [7l,7l+7) (identity beyond T). Local product -> Kogge-Stone suffix
//   scan (renormalized; q>0 invariant) -> exclusive carry -> exact local
//   replay. (b,c,kc) land in per-warp SMEM (no global bc round-trip).
// Forward: register KC state (lane kc&31 owns s0/s1); per trial all lanes
//   LDS-broadcast kc, owner lane reads (b,c) from SMEM, FFMA, writes m over
//   the b slot. Epilogue computes logits in place (stride-7 LDS: 7 coprime
//   32 -> conflict-free) and stores last_ability from registers.
// ---------------------------------------------------------------------------
__global__ void __launch_bounds__(256) scan_kernel(
    const int* __restrict__ q_id, const int* __restrict__ resp,
    const float* __restrict__ dmu, const float* __restrict__ smu,
    float* __restrict__ out)
{
    const int lane = threadIdx.x & 31;
    const int wid  = threadIdx.x >> 5;
    const int u = blockIdx.x * 8 + wid;
    const int base = lane * 7;

    __shared__ float sbm[8][T_DIM];          // b, then overwritten by m
    __shared__ float sc[8][T_DIM];           // c
    __shared__ int   skc[8][T_DIM];          // kc

    // ---- phase 1: load inputs for owned trials ----
    float mu[7], rr[7];
    int qv[7], kcv[7];
    #pragma unroll
    for (int j = 0; j < 7; j++) {
        int t = base + j;
        if (t < T_DIM) {
            int q  = q_id[u * T_DIM + t];
            int rs = resp[u * T_DIM + t];
            float2 f = d_tab[2 * q + rs];
            mu[j] = f.x; rr[j] = f.y;
            qv[j] = q;
            kcv[j] = d_kcq[q];
        } else { mu[j] = 0.0f; rr[j] = 0.0f; qv[j] = 0; kcv[j] = 0; }
    }

    // ---- local product S = M_base * ... * M_{base+6} ----
    float m00 = 1.0f, m01 = 0.0f, m10 = 0.0f, m11 = 1.0f;
    float m20 = 0.0f, m21 = 0.0f, m22 = 1.0f;
    #pragma unroll
    for (int j = 6; j >= 0; j--) {
        if (base + j < T_DIM) {
            float a = 2.0f + rr[j];
            float g = rr[j] * mu[j];
            float n00 = m10,                n01 = m11;
            float n10 = fmaf(a, m10, -m00);
            float n11 = fmaf(a, m11, -m01);
            float n20 = fmaf(g, m10, m20);
            float n21 = fmaf(g, m11, m21);
            m00 = n00; m01 = n01; m10 = n10; m11 = n11;
            m20 = n20; m21 = n21;
        }
    }

    // ---- inclusive suffix scan ----
    #pragma unroll
    for (int d = 1; d < 32; d <<= 1) {
        float b00 = __shfl_down_sync(0xFFFFFFFFu, m00, d);
        float b01 = __shfl_down_sync(0xFFFFFFFFu, m01, d);
        float b10 = __shfl_down_sync(0xFFFFFFFFu, m10, d);
        float b11 = __shfl_down_sync(0xFFFFFFFFu, m11, d);
        float b20 = __shfl_down_sync(0xFFFFFFFFu, m20, d);
        float b21 = __shfl_down_sync(0xFFFFFFFFu, m21, d);
        float b22 = __shfl_down_sync(0xFFFFFFFFu, m22, d);
        if (lane + d < 32) {
            float c00 = fmaf(m00, b00, m01 * b10);
            float c01 = fmaf(m00, b01, m01 * b11);
            float c10 = fmaf(m10, b00, m11 * b10);
            float c11 = fmaf(m10, b01, m11 * b11);
            float c20 = fmaf(m20, b00, fmaf(m21, b10, m22 * b20));
            float c21 = fmaf(m20, b01, fmaf(m21, b11, m22 * b21));
            float c22 = m22 * b22;
            float s = __fdividef(1.0f, fabsf(c10) + fabsf(c11) + 1e-30f);
            m00 = c00 * s; m01 = c01 * s;
            m10 = c10 * s; m11 = c11 * s;
            m20 = c20 * s; m21 = c21 * s; m22 = c22 * s;
        }
    }

    // ---- exclusive carry: P_l = T_{l+1}; lane 31 -> identity ----
    float p00 = __shfl_down_sync(0xFFFFFFFFu, m00, 1);
    float p01 = __shfl_down_sync(0xFFFFFFFFu, m01, 1);
    float p10 = __shfl_down_sync(0xFFFFFFFFu, m10, 1);
    float p11 = __shfl_down_sync(0xFFFFFFFFu, m11, 1);
    float p20 = __shfl_down_sync(0xFFFFFFFFu, m20, 1);
    float p21 = __shfl_down_sync(0xFFFFFFFFu, m21, 1);
    if (lane == 31) {
        p00 = 1.0f; p01 = 0.0f; p10 = 0.0f; p11 = 1.0f; p20 = 0.0f; p21 = 0.0f;
    }

    float pp = p00 + p01;
    float qq = p10 + p11;
    float ww = p20 + p21;
    float invq = __fdividef(1.0f, qq);
    float b = pp * invq;
    float c = ww * invq;

    // ---- local replay (exact reference arithmetic), write to SMEM ----
    #pragma unroll
    for (int j = 6; j >= 0; j--) {
        int t = base + j;
        if (t < T_DIM) {
            float bn = __fdividef(1.0f, 2.0f + rr[j] - b);
            c = bn * fmaf(rr[j], mu[j], c);
            b = bn;
            sbm[wid][t] = b;
            sc[wid][t] = c;
            skc[wid][t] = kcv[j];
        }
    }
    __syncwarp();

    // ---- phase 2: forward scan, register KC state ----
    float s0 = 0.0f, s1 = 0.0f;
    #pragma unroll 8
    for (int t = 0; t < T_DIM; t++) {
        int kj = skc[wid][t];
        if ((kj & 31) == lane) {
            float bj = sbm[wid][t];
            float cj = sc[wid][t];
            float s = (kj & 32) ? s1 : s0;
            float m = fmaf(bj, s, cj);
            if (kj & 32) s1 = m; else s0 = m;
            sbm[wid][t] = m;                 // m overwrites b (dead)
        }
    }
    __syncwarp();

    // ---- epilogue: logits (stride 7 -> bank-conflict-free LDS) ----
    #pragma unroll
    for (int j = 0; j < 7; j++) {
        int t = base + j;
        if (t < T_DIM) {
            float m = sbm[wid][t];
            int q = qv[j];
            out[u * T_DIM + t] = smu[q] * (m - dmu[q]);
        }
    }

    // last_ability_kc: (U, K); lane owns k=lane (s0) and k=lane+32 (s1)
    float* o2 = out + (size_t)U_DIM * T_DIM + (size_t)u * K_DIM;
    o2[lane] = s0;
    o2[32 + lane] = s1;
}

// ---------------------------------------------------------------------------
// Launch
// ---------------------------------------------------------------------------
extern "C" void kernel_launch(void* const* d_in, const int* in_sizes, int n_in,
                              void* d_out, int out_size)
{
    // metadata order: mask, q_id, kmap, resp, diff_mu, disc_mu, W1,b1,W2,b2,W3,b3
    const int* q_id = (const int*)d_in[1];
    const int* kmap = (const int*)d_in[2];
    const int* resp = (const int*)d_in[3];
    const float* dmu = (const float*)d_in[4];
    const float* smu = (const float*)d_in[5];
    const float* W1 = (const float*)d_in[6];
    const float* b1 = (const float*)d_in[7];
    const float* W2 = (const float*)d_in[8];
    const float* b2 = (const float*)d_in[9];
    const float* W3 = (const float*)d_in[10];
    const float* b3 = (const float*)d_in[11];
    float* out = (float*)d_out;

    // 2500 warps, one per 4 questions (8 (q,resp) tasks) -> 313 blocks of 256
    mlp_table_kernel<<<(Q_DIM / 4 + 7) / 8, 256>>>(dmu, smu, kmap,
                                                   W1, b1, W2, b2, W3, b3);
    scan_kernel<<<U_DIM / 8, 256>>>(q_id, resp, dmu, smu, out);
}

// round 13
// speedup vs baseline: 4.3402x; 1.0759x over previous
#include <cuda_runtime.h>
#include <cuda_bf16.h>
#include <math.h>

#define U_DIM 4096
#define T_DIM 200
#define K_DIM 64
#define Q_DIM 10000
#define H_DIM 128

typedef unsigned long long u64;

// Scratch (device globals; no allocation in kernel_launch)
__device__ float4 d_tab4[2 * Q_DIM];             // (mu, r, ts, ts*td) per (q,resp)
__device__ unsigned char d_kcq[Q_DIM];           // kc per question

__device__ __forceinline__ float gelu_exact(float x) {
    return 0.5f * x * (1.0f + erff(x * 0.70710678118654752440f));
}

__device__ __forceinline__ u64 pack2(float lo, float hi) {
    u64 r; asm("mov.b64 %0, {%1, %2};" : "=l"(r) : "f"(lo), "f"(hi)); return r;
}
__device__ __forceinline__ void unpack2(u64 v, float& lo, float& hi) {
    asm("mov.b64 {%0, %1}, %2;" : "=f"(lo), "=f"(hi) : "l"(v));
}
__device__ __forceinline__ u64 fma2(u64 a, u64 b, u64 c) {
    u64 d; asm("fma.rn.f32x2 %0, %1, %2, %3;" : "=l"(d) : "l"(a), "l"(b), "l"(c));
    return d;
}

// ---------------------------------------------------------------------------
// Kernel A: per-(q,resp) MLP table + kc_of_q.
// One warp per 8 tasks (4 questions x resp {0,1}).
// Layer-1 h staged in per-warp SMEM; layer-2 broadcasts h via UNIFORM-address
// LDS.128 (1 wavefront) instead of 4 SHFLs -> ~768 fewer instr/lane.
// Emits packed float4 records (mu, r, ts, ts*td) so the scan kernel needs a
// single 16B gather per trial. kmap is int32-upconverted bool: test != 0.
// ---------------------------------------------------------------------------
__global__ void __launch_bounds__(256) mlp_table_kernel(
    const float* __restrict__ dmu, const float* __restrict__ smu,
    const int* __restrict__ kmap,
    const float* __restrict__ W1, const float* __restrict__ b1,
    const float* __restrict__ W2, const float* __restrict__ b2,
    const float* __restrict__ W3, const float* __restrict__ b3)
{
    __shared__ float sh[8][8 * H_DIM];   // [warp][task*128 + unit]

    const int lane = threadIdx.x & 31;
    const int wid  = threadIdx.x >> 5;
    const int gw = (blockIdx.x * blockDim.x + threadIdx.x) >> 5;
    if (gw >= Q_DIM / 4) return;
    const int q0 = gw * 4;

    // ---- kc_of_q via ballot: warp owns questions q0..q0+3 ----
    #pragma unroll
    for (int j = 0; j < 4; j++) {
        int q = q0 + j;
        int vlo = kmap[q * K_DIM + lane];
        int vhi = kmap[q * K_DIM + 32 + lane];
        unsigned lo = __ballot_sync(0xFFFFFFFFu, vlo != 0);
        unsigned hi = __ballot_sync(0xFFFFFFFFu, vhi != 0);
        if (lane == 0) {
            int kc = lo ? (__ffs(lo) - 1) : (32 + __ffs(hi) - 1);
            d_kcq[q] = (unsigned char)kc;
        }
    }

    float x0[4], x1[4];
    #pragma unroll
    for (int j = 0; j < 4; j++) { x0[j] = dmu[q0 + j]; x1[j] = smu[q0 + j]; }

    // ---- layer 1: units 4*lane..4*lane+3; task tt: q=q0+(tt>>1), resp=tt&1 ----
    const float4 w10 = *(const float4*)(W1 + 0 * H_DIM + 4 * lane);
    const float4 w11 = *(const float4*)(W1 + 1 * H_DIM + 4 * lane);
    const float4 w12 = *(const float4*)(W1 + 2 * H_DIM + 4 * lane);
    const float4 b1v = *(const float4*)(b1 + 4 * lane);
    float r0[4] = {w10.x, w10.y, w10.z, w10.w};
    float r1[4] = {w11.x, w11.y, w11.z, w11.w};
    float r2[4] = {w12.x, w12.y, w12.z, w12.w};
    float bb[4] = {b1v.x, b1v.y, b1v.z, b1v.w};

    #pragma unroll
    for (int j = 0; j < 4; j++) {
        float4 h0, h1;
        float pre0 = fmaf(x0[j], r0[0], fmaf(x1[j], r1[0], bb[0]));
        float pre1 = fmaf(x0[j], r0[1], fmaf(x1[j], r1[1], bb[1]));
        float pre2 = fmaf(x0[j], r0[2], fmaf(x1[j], r1[2], bb[2]));
        float pre3 = fmaf(x0[j], r0[3], fmaf(x1[j], r1[3], bb[3]));
        h0.x = gelu_exact(pre0); h1.x = gelu_exact(pre0 + r2[0]);
        h0.y = gelu_exact(pre1); h1.y = gelu_exact(pre1 + r2[1]);
        h0.z = gelu_exact(pre2); h1.z = gelu_exact(pre2 + r2[2]);
        h0.w = gelu_exact(pre3); h1.w = gelu_exact(pre3 + r2[3]);
        *(float4*)&sh[wid][(2 * j) * H_DIM + 4 * lane] = h0;
        *(float4*)&sh[wid][(2 * j + 1) * H_DIM + 4 * lane] = h1;
    }
    __syncwarp();

    // ---- layer 2: 128x128 dense, FFMA2, uniform-LDS h broadcast ----
    const float4 b2v = *(const float4*)(b2 + 4 * lane);
    u64 accp[8][2];
    #pragma unroll
    for (int t = 0; t < 8; t++) {
        accp[t][0] = pack2(b2v.x, b2v.y);
        accp[t][1] = pack2(b2v.z, b2v.w);
    }
    #pragma unroll 2
    for (int base = 0; base < 32; base++) {
        u64 w2p[4][2];
        #pragma unroll
        for (int ii = 0; ii < 4; ii++) {
            const ulonglong2 wv =
                *(const ulonglong2*)(W2 + (base * 4 + ii) * H_DIM + 4 * lane);
            w2p[ii][0] = wv.x;
            w2p[ii][1] = wv.y;
        }
        #pragma unroll
        for (int t = 0; t < 8; t++) {
            float4 hv = *(const float4*)&sh[wid][t * H_DIM + base * 4]; // uniform
            u64 hp0 = pack2(hv.x, hv.x);
            u64 hp1 = pack2(hv.y, hv.y);
            u64 hp2 = pack2(hv.z, hv.z);
            u64 hp3 = pack2(hv.w, hv.w);
            accp[t][0] = fma2(hp0, w2p[0][0], accp[t][0]);
            accp[t][1] = fma2(hp0, w2p[0][1], accp[t][1]);
            accp[t][0] = fma2(hp1, w2p[1][0], accp[t][0]);
            accp[t][1] = fma2(hp1, w2p[1][1], accp[t][1]);
            accp[t][0] = fma2(hp2, w2p[2][0], accp[t][0]);
            accp[t][1] = fma2(hp2, w2p[2][1], accp[t][1]);
            accp[t][0] = fma2(hp3, w2p[3][0], accp[t][0]);
            accp[t][1] = fma2(hp3, w2p[3][1], accp[t][1]);
        }
    }
    float h2[8][4];
    #pragma unroll
    for (int t = 0; t < 8; t++) {
        float a0, a1, a2, a3;
        unpack2(accp[t][0], a0, a1);
        unpack2(accp[t][1], a2, a3);
        h2[t][0] = gelu_exact(a0);
        h2[t][1] = gelu_exact(a1);
        h2[t][2] = gelu_exact(a2);
        h2[t][3] = gelu_exact(a3);
    }

    // ---- layer 3: 128 -> 2, warp reduce ----
    const float4 w3a = *(const float4*)(W3 + 8 * lane);
    const float4 w3b = *(const float4*)(W3 + 8 * lane + 4);
    const float b30 = b3[0], b31 = b3[1];

    float o0[8], o1[8];
    #pragma unroll
    for (int t = 0; t < 8; t++) {
        o0[t] = fmaf(h2[t][0], w3a.x, fmaf(h2[t][1], w3a.z,
                fmaf(h2[t][2], w3b.x, h2[t][3] * w3b.z)));
        o1[t] = fmaf(h2[t][0], w3a.y, fmaf(h2[t][1], w3a.w,
                fmaf(h2[t][2], w3b.y, h2[t][3] * w3b.w)));
    }
    #pragma unroll
    for (int off = 16; off; off >>= 1) {
        #pragma unroll
        for (int t = 0; t < 8; t++) {
            o0[t] += __shfl_xor_sync(0xFFFFFFFFu, o0[t], off);
            o1[t] += __shfl_xor_sync(0xFFFFFFFFu, o1[t], off);
        }
    }
    if (lane == 0) {
        #pragma unroll
        for (int t = 0; t < 8; t++) {
            float mu = gelu_exact(o0[t] + b30);
            float lv = gelu_exact(o1[t] + b31);
            float s = fmaxf(expf(0.5f * lv), 1e-8f);
            float inv = 1.0f / s;
            int j = t >> 1;
            float ts = x1[j], td = x0[j];
            d_tab4[8 * gw + t] = make_float4(mu, inv * inv, ts, ts * td);
        }
    }
}

// ---------------------------------------------------------------------------
// Kernel B: FUSED backward Mobius scan + forward KC scan, warp-per-user.
//  - q/resp loaded COALESCED into smem (combined 2q+rs), segments re-read
//    stride-7 (gcd(7,32)=1 -> conflict-free).
//  - ONE 16B gather per trial (d_tab4) + 1B kc gather.
//  - Backward: homogeneous-linear suffix scan (Kogge-Stone, renormalized),
//    exact local replay from the carry.
//  - Forward: register KC state (lane kc&31 owns s0/s1) over smem (b,c,kc).
//  - Epilogue: logits = ts*m - ts*td staged in smem (dead sc), stored
//    COALESCED; last_ability from registers.
// ---------------------------------------------------------------------------
__global__ void __launch_bounds__(256) scan_kernel(
    const int* __restrict__ q_id, const int* __restrict__ resp,
    float* __restrict__ out)
{
    const int lane = threadIdx.x & 31;
    const int wid  = threadIdx.x >> 5;
    const int u = blockIdx.x * 8 + wid;
    const int base = lane * 7;

    __shared__ float sbm[8][T_DIM];          // b, then overwritten by m
    __shared__ float sc[8][T_DIM];           // c, then logits
    __shared__ int   skc[8][T_DIM];          // kc
    __shared__ int   sqr[8][224];            // 2*q+rs

    // ---- phase 0: coalesced loads of q/resp -> combined index in smem ----
    #pragma unroll
    for (int j = 0; j < 7; j++) {
        int t = j * 32 + lane;
        if (t < T_DIM) {
            int q  = q_id[u * T_DIM + t];
            int rs = resp[u * T_DIM + t];
            sqr[wid][t] = 2 * q + rs;
        }
    }
    __syncwarp();

    // ---- phase 1: gather packed trial records for owned segment ----
    float mu[7], rr[7], tsv[7], tdd[7];
    int kcv[7];
    #pragma unroll
    for (int j = 0; j < 7; j++) {
        int t = base + j;
        if (t < T_DIM) {
            int idx = sqr[wid][t];
            float4 f = d_tab4[idx];
            mu[j] = f.x; rr[j] = f.y; tsv[j] = f.z; tdd[j] = f.w;
            kcv[j] = d_kcq[idx >> 1];
        } else {
            mu[j] = 0.0f; rr[j] = 0.0f; tsv[j] = 0.0f; tdd[j] = 0.0f; kcv[j] = 0;
        }
    }

    // ---- local product S = M_base * ... * M_{base+6} ----
    float m00 = 1.0f, m01 = 0.0f, m10 = 0.0f, m11 = 1.0f;
    float m20 = 0.0f, m21 = 0.0f, m22 = 1.0f;
    #pragma unroll
    for (int j = 6; j >= 0; j--) {
        if (base + j < T_DIM) {
            float a = 2.0f + rr[j];
            float g = rr[j] * mu[j];
            float n00 = m10,                n01 = m11;
            float n10 = fmaf(a, m10, -m00);
            float n11 = fmaf(a, m11, -m01);
            float n20 = fmaf(g, m10, m20);
            float n21 = fmaf(g, m11, m21);
            m00 = n00; m01 = n01; m10 = n10; m11 = n11;
            m20 = n20; m21 = n21;
        }
    }

    // ---- inclusive suffix scan (renormalized; q>0 invariant) ----
    #pragma unroll
    for (int d = 1; d < 32; d <<= 1) {
        float b00 = __shfl_down_sync(0xFFFFFFFFu, m00, d);
        float b01 = __shfl_down_sync(0xFFFFFFFFu, m01, d);
        float b10 = __shfl_down_sync(0xFFFFFFFFu, m10, d);
        float b11 = __shfl_down_sync(0xFFFFFFFFu, m11, d);
        float b20 = __shfl_down_sync(0xFFFFFFFFu, m20, d);
        float b21 = __shfl_down_sync(0xFFFFFFFFu, m21, d);
        float b22 = __shfl_down_sync(0xFFFFFFFFu, m22, d);
        if (lane + d < 32) {
            float c00 = fmaf(m00, b00, m01 * b10);
            float c01 = fmaf(m00, b01, m01 * b11);
            float c10 = fmaf(m10, b00, m11 * b10);
            float c11 = fmaf(m10, b01, m11 * b11);
            float c20 = fmaf(m20, b00, fmaf(m21, b10, m22 * b20));
            float c21 = fmaf(m20, b01, fmaf(m21, b11, m22 * b21));
            float c22 = m22 * b22;
            float s = __fdividef(1.0f, fabsf(c10) + fabsf(c11) + 1e-30f);
            m00 = c00 * s; m01 = c01 * s;
            m10 = c10 * s; m11 = c11 * s;
            m20 = c20 * s; m21 = c21 * s; m22 = c22 * s;
        }
    }

    // ---- exclusive carry: P_l = T_{l+1}; lane 31 -> identity ----
    float p00 = __shfl_down_sync(0xFFFFFFFFu, m00, 1);
    float p01 = __shfl_down_sync(0xFFFFFFFFu, m01, 1);
    float p10 = __shfl_down_sync(0xFFFFFFFFu, m10, 1);
    float p11 = __shfl_down_sync(0xFFFFFFFFu, m11, 1);
    float p20 = __shfl_down_sync(0xFFFFFFFFu, m20, 1);
    float p21 = __shfl_down_sync(0xFFFFFFFFu, m21, 1);
    if (lane == 31) {
        p00 = 1.0f; p01 = 0.0f; p10 = 0.0f; p11 = 1.0f; p20 = 0.0f; p21 = 0.0f;
    }

    float pp = p00 + p01;
    float qq = p10 + p11;
    float ww = p20 + p21;
    float invq = __fdividef(1.0f, qq);
    float b = pp * invq;
    float c = ww * invq;

    // ---- local replay (exact reference arithmetic), write to SMEM ----
    #pragma unroll
    for (int j = 6; j >= 0; j--) {
        int t = base + j;
        if (t < T_DIM) {
            float bn = __fdividef(1.0f, 2.0f + rr[j] - b);
            c = bn * fmaf(rr[j], mu[j], c);
            b = bn;
            sbm[wid][t] = b;
            sc[wid][t] = c;
            skc[wid][t] = kcv[j];
        }
    }
    __syncwarp();

    // ---- phase 2: forward scan, register KC state ----
    float s0 = 0.0f, s1 = 0.0f;
    #pragma unroll 8
    for (int t = 0; t < T_DIM; t++) {
        int kj = skc[wid][t];
        if ((kj & 31) == lane) {
            float bj = sbm[wid][t];
            float cj = sc[wid][t];
            float s = (kj & 32) ? s1 : s0;
            float m = fmaf(bj, s, cj);
            if (kj & 32) s1 = m; else s0 = m;
            sbm[wid][t] = m;                 // m overwrites b (dead)
        }
    }
    __syncwarp();

    // ---- epilogue: logits staged to smem (sc is dead), stored coalesced ----
    #pragma unroll
    for (int j = 0; j < 7; j++) {
        int t = base + j;
        if (t < T_DIM) {
            float m = sbm[wid][t];
            sc[wid][t] = fmaf(tsv[j], m, -tdd[j]);   // ts*m - ts*td
        }
    }
    __syncwarp();
    #pragma unroll
    for (int j = 0; j < 7; j++) {
        int t = j * 32 + lane;
        if (t < T_DIM) out[u * T_DIM + t] = sc[wid][t];
    }

    // last_ability_kc: (U, K); lane owns k=lane (s0) and k=lane+32 (s1)
    float* o2 = out + (size_t)U_DIM * T_DIM + (size_t)u * K_DIM;
    o2[lane] = s0;
    o2[32 + lane] = s1;
}

// ---------------------------------------------------------------------------
// Launch
// ---------------------------------------------------------------------------
extern "C" void kernel_launch(void* const* d_in, const int* in_sizes, int n_in,
                              void* d_out, int out_size)
{
    // metadata order: mask, q_id, kmap, resp, diff_mu, disc_mu, W1,b1,W2,b2,W3,b3
    const int* q_id = (const int*)d_in[1];
    const int* kmap = (const int*)d_in[2];
    const int* resp = (const int*)d_in[3];
    const float* dmu = (const float*)d_in[4];
    const float* smu = (const float*)d_in[5];
    const float* W1 = (const float*)d_in[6];
    const float* b1 = (const float*)d_in[7];
    const float* W2 = (const float*)d_in[8];
    const float* b2 = (const float*)d_in[9];
    const float* W3 = (const float*)d_in[10];
    const float* b3 = (const float*)d_in[11];
    float* out = (float*)d_out;

    mlp_table_kernel<<<(Q_DIM / 4 + 7) / 8, 256>>>(dmu, smu, kmap,
                                                   W1, b1, W2, b2, W3, b3);
    scan_kernel<<<U_DIM / 8, 256>>>(q_id, resp, out);
}

// round 15
// speedup vs baseline: 4.5337x; 1.0446x over previous
#include <cuda_runtime.h>
#include <cuda_bf16.h>
#include <math.h>

#define U_DIM 4096
#define T_DIM 200
#define K_DIM 64
#define Q_DIM 10000
#define H_DIM 128

typedef unsigned long long u64;

// Scratch (device globals; no allocation in kernel_launch)
__device__ float4 d_tab4[2 * Q_DIM];             // (mu, r, ts, ts*td) per (q,resp)
__device__ unsigned char d_kcq[Q_DIM];           // kc per question

__device__ __forceinline__ float gelu_exact(float x) {
    return 0.5f * x * (1.0f + erff(x * 0.70710678118654752440f));
}

__device__ __forceinline__ u64 pack2(float lo, float hi) {
    u64 r; asm("mov.b64 %0, {%1, %2};" : "=l"(r) : "f"(lo), "f"(hi)); return r;
}
__device__ __forceinline__ void unpack2(u64 v, float& lo, float& hi) {
    asm("mov.b64 {%0, %1}, %2;" : "=f"(lo), "=f"(hi) : "l"(v));
}
__device__ __forceinline__ u64 fma2(u64 a, u64 b, u64 c) {
    u64 d; asm("fma.rn.f32x2 %0, %1, %2, %3;" : "=l"(d) : "l"(a), "l"(b), "l"(c));
    return d;
}

// ---------------------------------------------------------------------------
// Kernel A: per-(q,resp) MLP table + kc_of_q. One warp per 8 tasks
// (4 questions x resp {0,1}), 4 warps/block (32KB static smem).
// Layer-1 h stored DUPLICATED in smem (sh2[2i]=sh2[2i+1]=h_i) so layer-2
// fetches the FFMA2 operand (h_i,h_i) with ONE uniform LDS.64 -> no MOV
// packs (was ~2048 MOVs/warp). kmap is int32-upconverted bool.
// ---------------------------------------------------------------------------
__global__ void __launch_bounds__(128) mlp_table_kernel(
    const float* __restrict__ dmu, const float* __restrict__ smu,
    const int* __restrict__ kmap,
    const float* __restrict__ W1, const float* __restrict__ b1,
    const float* __restrict__ W2, const float* __restrict__ b2,
    const float* __restrict__ W3, const float* __restrict__ b3)
{
    __shared__ float sh2[4][8 * 2 * H_DIM];   // [warp][task*256 + 2*unit + {0,1}]

    const int lane = threadIdx.x & 31;
    const int wid  = threadIdx.x >> 5;
    const int gw = (blockIdx.x * blockDim.x + threadIdx.x) >> 5;
    if (gw >= Q_DIM / 4) return;
    const int q0 = gw * 4;

    // ---- kc_of_q via ballot: warp owns questions q0..q0+3 ----
    #pragma unroll
    for (int j = 0; j < 4; j++) {
        int q = q0 + j;
        int vlo = kmap[q * K_DIM + lane];
        int vhi = kmap[q * K_DIM + 32 + lane];
        unsigned lo = __ballot_sync(0xFFFFFFFFu, vlo != 0);
        unsigned hi = __ballot_sync(0xFFFFFFFFu, vhi != 0);
        if (lane == 0) {
            int kc = lo ? (__ffs(lo) - 1) : (32 + __ffs(hi) - 1);
            d_kcq[q] = (unsigned char)kc;
        }
    }

    float x0[4], x1[4];
    #pragma unroll
    for (int j = 0; j < 4; j++) { x0[j] = dmu[q0 + j]; x1[j] = smu[q0 + j]; }

    // ---- layer 1: units 4*lane..4*lane+3; task tt: q=q0+(tt>>1), resp=tt&1 ----
    const float4 w10 = *(const float4*)(W1 + 0 * H_DIM + 4 * lane);
    const float4 w11 = *(const float4*)(W1 + 1 * H_DIM + 4 * lane);
    const float4 w12 = *(const float4*)(W1 + 2 * H_DIM + 4 * lane);
    const float4 b1v = *(const float4*)(b1 + 4 * lane);
    float r0[4] = {w10.x, w10.y, w10.z, w10.w};
    float r1[4] = {w11.x, w11.y, w11.z, w11.w};
    float r2[4] = {w12.x, w12.y, w12.z, w12.w};
    float bb[4] = {b1v.x, b1v.y, b1v.z, b1v.w};

    #pragma unroll
    for (int j = 0; j < 4; j++) {
        float h0[4], h1[4];
        #pragma unroll
        for (int e = 0; e < 4; e++) {
            float pre = fmaf(x0[j], r0[e], fmaf(x1[j], r1[e], bb[e]));
            h0[e] = gelu_exact(pre);
            h1[e] = gelu_exact(pre + r2[e]);
        }
        // duplicated store: unit u at [2u] and [2u+1]
        float* p0 = &sh2[wid][(2 * j) * 2 * H_DIM + 8 * lane];
        float* p1 = &sh2[wid][(2 * j + 1) * 2 * H_DIM + 8 * lane];
        *(float4*)(p0)     = make_float4(h0[0], h0[0], h0[1], h0[1]);
        *(float4*)(p0 + 4) = make_float4(h0[2], h0[2], h0[3], h0[3]);
        *(float4*)(p1)     = make_float4(h1[0], h1[0], h1[1], h1[1]);
        *(float4*)(p1 + 4) = make_float4(h1[2], h1[2], h1[3], h1[3]);
    }
    __syncwarp();

    // ---- layer 2: 128x128 dense, FFMA2, duplicated-h uniform LDS.64 ----
    const float4 b2v = *(const float4*)(b2 + 4 * lane);
    u64 accp[8][2];
    #pragma unroll
    for (int t = 0; t < 8; t++) {
        accp[t][0] = pack2(b2v.x, b2v.y);
        accp[t][1] = pack2(b2v.z, b2v.w);
    }
    #pragma unroll 2
    for (int base = 0; base < 32; base++) {
        u64 w2p[4][2];
        #pragma unroll
        for (int ii = 0; ii < 4; ii++) {
            const ulonglong2 wv =
                *(const ulonglong2*)(W2 + (base * 4 + ii) * H_DIM + 4 * lane);
            w2p[ii][0] = wv.x;
            w2p[ii][1] = wv.y;
        }
        #pragma unroll
        for (int t = 0; t < 8; t++) {
            const float* hb = &sh2[wid][t * 2 * H_DIM + 8 * base]; // uniform addr
            #pragma unroll
            for (int ii = 0; ii < 4; ii++) {
                u64 hp = *(const u64*)(hb + 2 * ii);   // (h_i, h_i) via LDS.64
                accp[t][0] = fma2(hp, w2p[ii][0], accp[t][0]);
                accp[t][1] = fma2(hp, w2p[ii][1], accp[t][1]);
            }
        }
    }
    float h2[8][4];
    #pragma unroll
    for (int t = 0; t < 8; t++) {
        float a0, a1, a2, a3;
        unpack2(accp[t][0], a0, a1);
        unpack2(accp[t][1], a2, a3);
        h2[t][0] = gelu_exact(a0);
        h2[t][1] = gelu_exact(a1);
        h2[t][2] = gelu_exact(a2);
        h2[t][3] = gelu_exact(a3);
    }

    // ---- layer 3: 128 -> 2, warp reduce ----
    const float4 w3a = *(const float4*)(W3 + 8 * lane);
    const float4 w3b = *(const float4*)(W3 + 8 * lane + 4);
    const float b30 = b3[0], b31 = b3[1];

    float o0[8], o1[8];
    #pragma unroll
    for (int t = 0; t < 8; t++) {
        o0[t] = fmaf(h2[t][0], w3a.x, fmaf(h2[t][1], w3a.z,
                fmaf(h2[t][2], w3b.x, h2[t][3] * w3b.z)));
        o1[t] = fmaf(h2[t][0], w3a.y, fmaf(h2[t][1], w3a.w,
                fmaf(h2[t][2], w3b.y, h2[t][3] * w3b.w)));
    }
    #pragma unroll
    for (int off = 16; off; off >>= 1) {
        #pragma unroll
        for (int t = 0; t < 8; t++) {
            o0[t] += __shfl_xor_sync(0xFFFFFFFFu, o0[t], off);
            o1[t] += __shfl_xor_sync(0xFFFFFFFFu, o1[t], off);
        }
    }
    if (lane == 0) {
        #pragma unroll
        for (int t = 0; t < 8; t++) {
            float mu = gelu_exact(o0[t] + b30);
            float lv = gelu_exact(o1[t] + b31);
            float s = fmaxf(expf(0.5f * lv), 1e-8f);
            float inv = 1.0f / s;
            int j = t >> 1;
            float ts = x1[j], td = x0[j];
            d_tab4[8 * gw + t] = make_float4(mu, inv * inv, ts, ts * td);
        }
    }
}

// ---------------------------------------------------------------------------
// Kernel B: FUSED backward Mobius scan + forward KC scan, warp-per-user.
// Phase 2 wavefront diet: kc packed as BYTES (one uniform LDS.32 per 4
// trials), (b,c) fused to float2 (one LDS.64), m overwrites bc.x.
// ---------------------------------------------------------------------------
__global__ void __launch_bounds__(256) scan_kernel(
    const int* __restrict__ q_id, const int* __restrict__ resp,
    float* __restrict__ out)
{
    const int lane = threadIdx.x & 31;
    const int wid  = threadIdx.x >> 5;
    const int u = blockIdx.x * 8 + wid;
    const int base = lane * 7;

    __shared__ float2 sbc[8][T_DIM];         // (b, c); m overwrites .x
    __shared__ unsigned int skcw[8][56];     // kc bytes (224 padded)
    __shared__ int sqr[8][224];              // 2*q+rs, then logits (reused)

    unsigned char* skc = (unsigned char*)&skcw[wid][0];

    // ---- phase 0: coalesced q/resp -> combined index in smem ----
    #pragma unroll
    for (int j = 0; j < 7; j++) {
        int t = j * 32 + lane;
        if (t < T_DIM) {
            int q  = q_id[u * T_DIM + t];
            int rs = resp[u * T_DIM + t];
            sqr[wid][t] = 2 * q + rs;
        }
    }
    __syncwarp();

    // ---- phase 1: gather packed trial records for owned segment ----
    float mu[7], rr[7], tsv[7], tdd[7];
    int kcv[7];
    #pragma unroll
    for (int j = 0; j < 7; j++) {
        int t = base + j;
        if (t < T_DIM) {
            int idx = sqr[wid][t];
            float4 f = d_tab4[idx];
            mu[j] = f.x; rr[j] = f.y; tsv[j] = f.z; tdd[j] = f.w;
            kcv[j] = d_kcq[idx >> 1];
        } else {
            mu[j] = 0.0f; rr[j] = 0.0f; tsv[j] = 0.0f; tdd[j] = 0.0f; kcv[j] = 0;
        }
    }

    // ---- local product S = M_base * ... * M_{base+6} ----
    float m00 = 1.0f, m01 = 0.0f, m10 = 0.0f, m11 = 1.0f;
    float m20 = 0.0f, m21 = 0.0f, m22 = 1.0f;
    #pragma unroll
    for (int j = 6; j >= 0; j--) {
        if (base + j < T_DIM) {
            float a = 2.0f + rr[j];
            float g = rr[j] * mu[j];
            float n00 = m10,                n01 = m11;
            float n10 = fmaf(a, m10, -m00);
            float n11 = fmaf(a, m11, -m01);
            float n20 = fmaf(g, m10, m20);
            float n21 = fmaf(g, m11, m21);
            m00 = n00; m01 = n01; m10 = n10; m11 = n11;
            m20 = n20; m21 = n21;
        }
    }

    // ---- inclusive suffix scan (renormalized; q>0 invariant) ----
    #pragma unroll
    for (int d = 1; d < 32; d <<= 1) {
        float b00 = __shfl_down_sync(0xFFFFFFFFu, m00, d);
        float b01 = __shfl_down_sync(0xFFFFFFFFu, m01, d);
        float b10 = __shfl_down_sync(0xFFFFFFFFu, m10, d);
        float b11 = __shfl_down_sync(0xFFFFFFFFu, m11, d);
        float b20 = __shfl_down_sync(0xFFFFFFFFu, m20, d);
        float b21 = __shfl_down_sync(0xFFFFFFFFu, m21, d);
        float b22 = __shfl_down_sync(0xFFFFFFFFu, m22, d);
        if (lane + d < 32) {
            float c00 = fmaf(m00, b00, m01 * b10);
            float c01 = fmaf(m00, b01, m01 * b11);
            float c10 = fmaf(m10, b00, m11 * b10);
            float c11 = fmaf(m10, b01, m11 * b11);
            float c20 = fmaf(m20, b00, fmaf(m21, b10, m22 * b20));
            float c21 = fmaf(m20, b01, fmaf(m21, b11, m22 * b21));
            float c22 = m22 * b22;
            float s = __fdividef(1.0f, fabsf(c10) + fabsf(c11) + 1e-30f);
            m00 = c00 * s; m01 = c01 * s;
            m10 = c10 * s; m11 = c11 * s;
            m20 = c20 * s; m21 = c21 * s; m22 = c22 * s;
        }
    }

    // ---- exclusive carry: P_l = T_{l+1}; lane 31 -> identity ----
    float p00 = __shfl_down_sync(0xFFFFFFFFu, m00, 1);
    float p01 = __shfl_down_sync(0xFFFFFFFFu, m01, 1);
    float p10 = __shfl_down_sync(0xFFFFFFFFu, m10, 1);
    float p11 = __shfl_down_sync(0xFFFFFFFFu, m11, 1);
    float p20 = __shfl_down_sync(0xFFFFFFFFu, m20, 1);
    float p21 = __shfl_down_sync(0xFFFFFFFFu, m21, 1);
    if (lane == 31) {
        p00 = 1.0f; p01 = 0.0f; p10 = 0.0f; p11 = 1.0f; p20 = 0.0f; p21 = 0.0f;
    }

    float pp = p00 + p01;
    float qq = p10 + p11;
    float ww = p20 + p21;
    float invq = __fdividef(1.0f, qq);
    float b = pp * invq;
    float c = ww * invq;

    // ---- local replay (exact reference arithmetic), write to SMEM ----
    #pragma unroll
    for (int j = 6; j >= 0; j--) {
        int t = base + j;
        if (t < T_DIM) {
            float bn = __fdividef(1.0f, 2.0f + rr[j] - b);
            c = bn * fmaf(rr[j], mu[j], c);
            b = bn;
            sbc[wid][t] = make_float2(b, c);
            skc[t] = (unsigned char)kcv[j];
        }
    }
    __syncwarp();

    // ---- phase 2: forward scan, register KC state, byte-packed kc ----
    float s0 = 0.0f, s1 = 0.0f;
    #pragma unroll 5
    for (int g = 0; g < T_DIM / 4; g++) {
        unsigned int kw = skcw[wid][g];          // uniform LDS.32: 4 kc's
        #pragma unroll
        for (int j = 0; j < 4; j++) {
            int t = 4 * g + j;
            int kj = (kw >> (8 * j)) & 0xFF;
            if ((kj & 31) == lane) {
                float2 bc = sbc[wid][t];
                float s = (kj & 32) ? s1 : s0;
                float m = fmaf(bc.x, s, bc.y);
                if (kj & 32) s1 = m; else s0 = m;
                sbc[wid][t].x = m;               // m overwrites b (dead)
            }
        }
    }
    __syncwarp();

    // ---- epilogue: logits staged to smem (sqr is dead), stored coalesced ----
    float* slog = (float*)&sqr[wid][0];
    #pragma unroll
    for (int j = 0; j < 7; j++) {
        int t = base + j;
        if (t < T_DIM) {
            float m = sbc[wid][t].x;
            slog[t] = fmaf(tsv[j], m, -tdd[j]);  // ts*m - ts*td
        }
    }
    __syncwarp();
    #pragma unroll
    for (int j = 0; j < 7; j++) {
        int t = j * 32 + lane;
        if (t < T_DIM) out[u * T_DIM + t] = slog[t];
    }

    // last_ability_kc: (U, K); lane owns k=lane (s0) and k=lane+32 (s1)
    float* o2 = out + (size_t)U_DIM * T_DIM + (size_t)u * K_DIM;
    o2[lane] = s0;
    o2[32 + lane] = s1;
}

// ---------------------------------------------------------------------------
// Launch
// ---------------------------------------------------------------------------
extern "C" void kernel_launch(void* const* d_in, const int* in_sizes, int n_in,
                              void* d_out, int out_size)
{
    // metadata order: mask, q_id, kmap, resp, diff_mu, disc_mu, W1,b1,W2,b2,W3,b3
    const int* q_id = (const int*)d_in[1];
    const int* kmap = (const int*)d_in[2];
    const int* resp = (const int*)d_in[3];
    const float* dmu = (const float*)d_in[4];
    const float* smu = (const float*)d_in[5];
    const float* W1 = (const float*)d_in[6];
    const float* b1 = (const float*)d_in[7];
    const float* W2 = (const float*)d_in[8];
    const float* b2 = (const float*)d_in[9];
    const float* W3 = (const float*)d_in[10];
    const float* b3 = (const float*)d_in[11];
    float* out = (float*)d_out;

    // 2500 warps, 4 warps/block (32KB static smem each)
    mlp_table_kernel<<<(Q_DIM / 4 + 3) / 4, 128>>>(dmu, smu, kmap,
                                                   W1, b1, W2, b2, W3, b3);
    scan_kernel<<<U_DIM / 8, 256>>>(q_id, resp, out);
}